// round 11
// baseline (speedup 1.0000x reference)
#include <cuda_runtime.h>
#include <cuda_bf16.h>
#include <cstdint>

#define NSAMP 65536
#define BORIG 32768
#define TT    15
#define KPA   290
#define KPB   306
typedef unsigned long long u64;

__device__ u64   g_xT[(size_t)30 * NSAMP];
__device__ u64   g_l0u[(size_t)2 * TT * 32 * NSAMP];
__device__ float g_last[(size_t)2 * 64 * NSAMP];

__device__ __forceinline__ u64 pack2(float lo, float hi) {
    u64 r; asm("mov.b64 %0, {%1, %2};" : "=l"(r) : "r"(__float_as_uint(lo)), "r"(__float_as_uint(hi))); return r;
}
__device__ __forceinline__ void unpack2(u64 a, float& lo, float& hi) {
    unsigned x, y; asm("mov.b64 {%0, %1}, %2;" : "=r"(x), "=r"(y) : "l"(a));
    lo = __uint_as_float(x); hi = __uint_as_float(y);
}
__device__ __forceinline__ void fma2(u64& d, u64 a, u64 b) {
    asm("fma.rn.f32x2 %0, %1, %2, %0;" : "+l"(d) : "l"(a), "l"(b));
}
__device__ __forceinline__ float usum(u64 a) { float lo, hi; unpack2(a, lo, hi); return lo + hi; }
__device__ __forceinline__ float tanhx(float x) { float r; asm("tanh.approx.f32 %0, %1;" : "=f"(r) : "f"(x)); return r; }
__device__ __forceinline__ float sigf(float x) { return fmaf(0.5f, tanhx(0.5f * x), 0.5f); }
__device__ __forceinline__ uint32_t bpack(float lo, float hi) {   // lo -> low half
    uint32_t r; asm("cvt.rn.bf16x2.f32 %0, %1, %2;" : "=r"(r) : "f"(hi), "f"(lo)); return r;
}
__device__ __forceinline__ float bf16v(float x) { return __bfloat162float(__float2bfloat16(x)); }

__device__ __forceinline__ void mma16816(float* d, const uint32_t* a, const uint32_t* b) {
    asm volatile("mma.sync.aligned.m16n8k16.row.col.f32.bf16.bf16.f32 "
        "{%0,%1,%2,%3}, {%4,%5,%6,%7}, {%8,%9}, {%0,%1,%2,%3};"
        : "+f"(d[0]), "+f"(d[1]), "+f"(d[2]), "+f"(d[3])
        : "r"(a[0]), "r"(a[1]), "r"(a[2]), "r"(a[3]), "r"(b[0]), "r"(b[1]));
}

// ---------------- transpose (unchanged) ----------------
__global__ void __launch_bounds__(128) k_transpose(const float* __restrict__ pos)
{
    __shared__ float sx[128 * 60];
    const unsigned s0 = blockIdx.x * 128u;
    for (int idx = threadIdx.x; idx < 128 * 60; idx += 128) {
        int i = idx / 60, f = idx % 60;
        unsigned s = s0 + i;
        sx[idx] = pos[s < BORIG ? (size_t)s * 120 + f : (size_t)(s - BORIG) * 120 + 60 + f];
    }
    __syncthreads();
    const int i = threadIdx.x;
#pragma unroll
    for (int u = 0; u < 30; ++u) {
        int t = u >> 1, p = u & 1;
        g_xT[(size_t)u * NSAMP + s0 + i] = pack2(sx[i * 60 + t * 4 + p * 2], sx[i * 60 + t * 4 + p * 2 + 1]);
    }
}

// ---------------- layer0 FFMA N=4 (unchanged) ----------------
__global__ void __launch_bounds__(128) lstm_layer0(
    const float* __restrict__ lWih, const float* __restrict__ lWhh, const float* __restrict__ lb,
    const float* __restrict__ vWih, const float* __restrict__ vWhh, const float* __restrict__ vb)
{
    __shared__ __align__(16) float sWf[128 * 36];
    __shared__ float sB[128];
    const int d = blockIdx.y, br = blockIdx.z;
    const float* Wih = (br ? vWih : lWih) + d * 128 * 4;
    const float* Whh = (br ? vWhh : lWhh) + d * 128 * 32;
    const float* bb  = (br ? vb   : lb  ) + d * 128;
    for (int idx = threadIdx.x; idx < 128 * 36; idx += 128) {
        int r = idx / 36, o = idx % 36;
        sWf[idx] = (o < 4) ? Wih[r * 4 + o] : Whh[r * 32 + (o - 4)];
    }
    sB[threadIdx.x] = bb[threadIdx.x];
    __syncthreads();
    const u64* sW = reinterpret_cast<const u64*>(sWf);
    const unsigned s0 = blockIdx.x * 512u + threadIdx.x;
    u64 v2[4][18];
    float c[4][32], hn[4][32];
#pragma unroll
    for (int n = 0; n < 4; ++n)
#pragma unroll
        for (int k = 2; k < 18; ++k) v2[n][k] = 0;
#pragma unroll 1
    for (int j = 0; j < 32; ++j)
#pragma unroll
        for (int n = 0; n < 4; ++n) c[n][j] = 0.f;
    for (int step = 0; step < TT; ++step) {
        const int t = d ? (TT - 1 - step) : step;
#pragma unroll
        for (int n = 0; n < 4; ++n) {
            v2[n][0] = g_xT[(size_t)(t * 2) * NSAMP + s0 + n * 128];
            v2[n][1] = g_xT[(size_t)(t * 2 + 1) * NSAMP + s0 + n * 128];
        }
#pragma unroll 1
        for (int j = 0; j < 32; ++j) {
            u64 acc[4][4];
#pragma unroll
            for (int g = 0; g < 4; ++g)
#pragma unroll
                for (int n = 0; n < 4; ++n) acc[g][n] = 0;
#pragma unroll
            for (int g = 0; g < 4; ++g) {
                const ulonglong2* row = reinterpret_cast<const ulonglong2*>(sW + (size_t)(j + 32 * g) * 18);
#pragma unroll
                for (int k2 = 0; k2 < 9; ++k2) {
                    ulonglong2 w = row[k2];
#pragma unroll
                    for (int n = 0; n < 4; ++n) {
                        fma2(acc[g][n], w.x, v2[n][2 * k2]);
                        fma2(acc[g][n], w.y, v2[n][2 * k2 + 1]);
                    }
                }
            }
            float bi = sB[j], bf = sB[j + 32], bg = sB[j + 64], bo = sB[j + 96];
#pragma unroll
            for (int n = 0; n < 4; ++n) {
                float iv = usum(acc[0][n]) + bi, fv = usum(acc[1][n]) + bf;
                float gv = usum(acc[2][n]) + bg, ov = usum(acc[3][n]) + bo;
                float cn = sigf(fv) * c[n][j] + sigf(iv) * tanhx(gv);
                c[n][j] = cn;
                hn[n][j] = sigf(ov) * tanhx(cn);
            }
        }
        u64* gb = g_l0u + ((size_t)(br * TT + t) * 32 + d * 16) * NSAMP;
#pragma unroll
        for (int q = 0; q < 16; ++q)
#pragma unroll
            for (int n = 0; n < 4; ++n) {
                u64 hp = pack2(hn[n][2 * q], hn[n][2 * q + 1]);
                v2[n][2 + q] = hp;
                gb[(size_t)q * NSAMP + s0 + n * 128] = hp;
            }
    }
}

// ---------------- layer1: mma.sync bf16 hi/lo ----------------
// A[s][k]: [0..63]=x_hi [64..95]=h_hi [96..159]=x_lo [160..191]=h_lo [192..255]=x_hi' [256..287]=h_hi'
//          [288,289]=(1,1) bias lanes.  B[r][k]: [0..191]=w_hi, [192..287]=w_lo, [288]=b_hi [289]=b_lo.
#define AOFF  0
#define BFOFF (128 * KPA)
#define BBOFF (BFOFF + 128 * KPB)
#define SMEM_L1 ((BBOFF + 128 * KPB) * 2)

__device__ __forceinline__ void mma_main(float d[2][16][4], const uint32_t* A32, const uint32_t* B32,
                                         int w, int l)
{
    const int r0 = 32 * w + (l >> 2);
    const int kb = (l & 3) * 2;
#pragma unroll 1
    for (int kt = 0; kt < 19; ++kt) {
        const int k0 = kt * 16 + kb;
        uint32_t a[2][4];
#pragma unroll
        for (int mt = 0; mt < 2; ++mt) {
            int ra = (r0 + 16 * mt) * KPA + k0, rb = ra + 8 * KPA;
            a[mt][0] = A32[ra >> 1];       a[mt][1] = A32[rb >> 1];
            a[mt][2] = A32[(ra + 8) >> 1]; a[mt][3] = A32[(rb + 8) >> 1];
        }
#pragma unroll
        for (int nh = 0; nh < 2; ++nh) {
            uint32_t bf[8][2];
#pragma unroll
            for (int q = 0; q < 8; ++q) {
                int ba = ((nh * 8 + q) * 8 + (l >> 2)) * KPB + k0;
                bf[q][0] = B32[ba >> 1]; bf[q][1] = B32[(ba + 8) >> 1];
            }
#pragma unroll
            for (int mt = 0; mt < 2; ++mt)
#pragma unroll
                for (int q = 0; q < 8; ++q)
                    mma16816(d[mt][nh * 8 + q], a[mt], bf[q]);
        }
    }
}

__global__ void __launch_bounds__(128) mma_layer1(
    const float* __restrict__ lWih, const float* __restrict__ lWhh, const float* __restrict__ lb,
    const float* __restrict__ vWih, const float* __restrict__ vWhh, const float* __restrict__ vb)
{
    extern __shared__ __align__(16) __nv_bfloat16 sm[];
    uint32_t* A32 = reinterpret_cast<uint32_t*>(sm);
    const uint32_t* BF32 = reinterpret_cast<const uint32_t*>(sm + BFOFF);
    const uint32_t* BB32 = reinterpret_cast<const uint32_t*>(sm + BBOFF);
    const int tid = threadIdx.x, w = tid >> 5, l = tid & 31;
    const int br = blockIdx.y;
    const unsigned s0 = blockIdx.x * 128u;
    const float* Wih = br ? vWih : lWih;
    const float* Whh = br ? vWhh : lWhh;
    const float* bbp = br ? vb : lb;

    for (int idx = tid; idx < 128 * KPB; idx += 128) {       // fwd B
        int r = idx / KPB, k = idx % KPB;
        float wv = 0.f; int m = 0;
        if (k < 288) { int kk = (k < 192) ? (k % 96) : (k - 192);
                       wv = (kk < 64) ? Wih[r * 64 + kk] : Whh[r * 32 + kk - 64];
                       m = (k < 192) ? 1 : 2; }
        else if (k == 288) { wv = bbp[r]; m = 1; }
        else if (k == 289) { wv = bbp[r]; m = 2; }
        sm[BFOFF + r * KPB + k] = __float2bfloat16(m == 0 ? 0.f : (m == 1 ? wv : wv - bf16v(wv)));
    }
    for (int idx = tid; idx < 128 * KPB; idx += 128) {       // bwd B (h slots zero)
        int r = idx / KPB, k = idx % KPB;
        float wv = 0.f; int m = 0;
        if (k < 64)                { wv = Wih[128 * 64 + r * 64 + k];        m = 1; }
        else if (k >= 96 && k < 160) { wv = Wih[128 * 64 + r * 64 + k - 96]; m = 1; }
        else if (k >= 192 && k < 256) { wv = Wih[128 * 64 + r * 64 + k - 192]; m = 2; }
        else if (k == 288) { wv = bbp[128 + r]; m = 1; }
        else if (k == 289) { wv = bbp[128 + r]; m = 2; }
        sm[BBOFF + r * KPB + k] = __float2bfloat16(m == 0 ? 0.f : (m == 1 ? wv : wv - bf16v(wv)));
    }
    for (int idx = tid; idx < 128 * KPA / 2; idx += 128) A32[idx] = 0;
    __syncthreads();
    A32[(tid * KPA + 288) >> 1] = 0x3F803F80u;               // (1.0, 1.0) bias lanes
    __syncthreads();

    float c[2][2][4][2];
#pragma unroll
    for (int a = 0; a < 2; ++a)
#pragma unroll
        for (int b = 0; b < 2; ++b)
#pragma unroll
            for (int g = 0; g < 4; ++g) { c[a][b][g][0] = 0.f; c[a][b][g][1] = 0.f; }

#pragma unroll 1
    for (int t = 0; t < TT; ++t) {
        const u64* gx = g_l0u + (size_t)(br * TT + t) * 32 * NSAMP + s0 + tid;
#pragma unroll
        for (int kp = 0; kp < 32; ++kp) {                    // stage x hi/lo/dup
            float f0, f1; unpack2(gx[(size_t)kp * NSAMP], f0, f1);
            float h0 = bf16v(f0), h1 = bf16v(f1);
            uint32_t hi = bpack(h0, h1), lo = bpack(f0 - h0, f1 - h1);
            A32[(tid * KPA) / 2 + kp] = hi;
            A32[(tid * KPA + 96) / 2 + kp] = lo;
            A32[(tid * KPA + 192) / 2 + kp] = hi;
        }
        __syncthreads();

        float d[2][16][4];
#pragma unroll
        for (int mt = 0; mt < 2; ++mt)
#pragma unroll
            for (int nt = 0; nt < 16; ++nt)
#pragma unroll
                for (int q = 0; q < 4; ++q) d[mt][nt][q] = 0.f;
        mma_main(d, A32, BF32, w, l);
        __syncthreads();                                     // all reads done before h writes

#pragma unroll
        for (int mt = 0; mt < 2; ++mt)
#pragma unroll
            for (int hp = 0; hp < 2; ++hp)
#pragma unroll
                for (int g4 = 0; g4 < 4; ++g4) {
                    float hv[2];
#pragma unroll
                    for (int col = 0; col < 2; ++col) {
                        int e = hp * 2 + col;
                        float ci = d[mt][g4][e], cf = d[mt][g4 + 4][e];
                        float cg = d[mt][g4 + 8][e], co = d[mt][g4 + 12][e];
                        float cc = c[mt][hp][g4][col];
                        cc = sigf(cf) * cc + sigf(ci) * tanhx(cg);
                        c[mt][hp][g4][col] = cc;
                        hv[col] = sigf(co) * tanhx(cc);
                    }
                    int srow = 32 * w + 16 * mt + (l >> 2) + 8 * hp;
                    int jp = 8 * g4 + (l & 3) * 2;
                    if (t < TT - 1) {
                        float b0 = bf16v(hv[0]), b1 = bf16v(hv[1]);
                        A32[(srow * KPA + 64 + jp) >> 1]  = bpack(b0, b1);
                        A32[(srow * KPA + 160 + jp) >> 1] = bpack(hv[0] - b0, hv[1] - b1);
                        A32[(srow * KPA + 256 + jp) >> 1] = bpack(b0, b1);
                    } else {
                        g_last[((size_t)br * 64 + jp) * NSAMP + s0 + srow]     = hv[0];
                        g_last[((size_t)br * 64 + jp + 1) * NSAMP + s0 + srow] = hv[1];
                    }
                }
    }
    __syncthreads();

    // bwd single step: x14 already staged in A; h-slots killed by BB zeros; c0 = 0
    float d[2][16][4];
#pragma unroll
    for (int mt = 0; mt < 2; ++mt)
#pragma unroll
        for (int nt = 0; nt < 16; ++nt)
#pragma unroll
            for (int q = 0; q < 4; ++q) d[mt][nt][q] = 0.f;
    mma_main(d, A32, BB32, w, l);
#pragma unroll
    for (int mt = 0; mt < 2; ++mt)
#pragma unroll
        for (int hp = 0; hp < 2; ++hp)
#pragma unroll
            for (int g4 = 0; g4 < 4; ++g4) {
                int srow = 32 * w + 16 * mt + (l >> 2) + 8 * hp;
                int jp = 8 * g4 + (l & 3) * 2;
#pragma unroll
                for (int col = 0; col < 2; ++col) {
                    int e = hp * 2 + col;
                    float cn = sigf(d[mt][g4][e]) * tanhx(d[mt][g4 + 8][e]);
                    g_last[((size_t)br * 64 + 32 + jp + col) * NSAMP + s0 + srow] =
                        sigf(d[mt][g4 + 12][e]) * tanhx(cn);
                }
            }
}

// ---------------- head (unchanged) ----------------
__global__ void __launch_bounds__(128) head_kernel(
    const float* __restrict__ dir,
    const float* __restrict__ lW, const float* __restrict__ lbias,
    const float* __restrict__ vW, const float* __restrict__ vbias,
    float* __restrict__ out)
{
    const int b = blockIdx.x * 128 + threadIdx.x;
    if (b >= BORIG) return;
    const float* di = dir + (size_t)b * 6;
    int am = 0; float mv = di[0];
#pragma unroll
    for (int i = 1; i < 6; ++i) { float x = di[i]; if (x > mv) { mv = x; am = i; } }
    const float m_vor = (am == 1 || am == 4) ? 1.f : 0.f;
    const float m_r   = (am == 0 || am == 5) ? 1.f : 0.f;
    const float m_l   = (am == 2 || am == 3) ? 1.f : 0.f;
    const float* ll = g_last + b;
    const float* lr = g_last + b + BORIG;
    const float* vl = g_last + (size_t)64 * NSAMP + b;
    const float* vr = g_last + (size_t)64 * NSAMP + b + BORIG;
    float xr0 = lbias[0], xr1 = lbias[1], xl0 = lbias[0], xl1 = lbias[1];
#pragma unroll
    for (int k = 0; k < 64; ++k) {
        float w0 = lW[k], w1 = lW[64 + k];
        float a = lr[(size_t)k * NSAMP], bb2 = ll[(size_t)k * NSAMP];
        xr0 = fmaf(a, w0, xr0); xr1 = fmaf(a, w1, xr1);
        xl0 = fmaf(bb2, w0, xl0); xl1 = fmaf(bb2, w1, xl1);
    }
    float xv0 = vbias[0], xv1 = vbias[1];
#pragma unroll
    for (int k = 0; k < 64; ++k) {
        float a = vl[(size_t)k * NSAMP];
        xv0 = fmaf(a, vW[k], xv0); xv1 = fmaf(a, vW[128 + k], xv1);
    }
#pragma unroll
    for (int k = 0; k < 64; ++k) {
        float a = vr[(size_t)k * NSAMP];
        xv0 = fmaf(a, vW[64 + k], xv0); xv1 = fmaf(a, vW[192 + k], xv1);
    }
    out[2 * b]     = xr0 * m_r + xl0 * m_l + xv0 * m_vor;
    out[2 * b + 1] = xr1 * m_r + xl1 * m_l + xv1 * m_vor;
}

extern "C" void kernel_launch(void* const* d_in, const int* in_sizes, int n_in,
                              void* d_out, int out_size)
{
    (void)in_sizes; (void)n_in; (void)out_size;
    const float* dir   = (const float*)d_in[0];
    const float* pos   = (const float*)d_in[1];
    const float* lWih0 = (const float*)d_in[2];
    const float* lWhh0 = (const float*)d_in[3];
    const float* lb0   = (const float*)d_in[4];
    const float* lWih1 = (const float*)d_in[5];
    const float* lWhh1 = (const float*)d_in[6];
    const float* lb1   = (const float*)d_in[7];
    const float* vWih0 = (const float*)d_in[8];
    const float* vWhh0 = (const float*)d_in[9];
    const float* vb0   = (const float*)d_in[10];
    const float* vWih1 = (const float*)d_in[11];
    const float* vWhh1 = (const float*)d_in[12];
    const float* vb1   = (const float*)d_in[13];
    const float* lfcW  = (const float*)d_in[14];
    const float* lfcb  = (const float*)d_in[15];
    const float* vfcW  = (const float*)d_in[16];
    const float* vfcb  = (const float*)d_in[17];
    float* out = (float*)d_out;

    cudaFuncSetAttribute(mma_layer1, cudaFuncAttributeMaxDynamicSharedMemorySize, SMEM_L1);

    k_transpose<<<NSAMP / 128, 128>>>(pos);
    lstm_layer0<<<dim3(NSAMP / 512, 2, 2), 128>>>(lWih0, lWhh0, lb0, vWih0, vWhh0, vb0);
    mma_layer1<<<dim3(NSAMP / 128, 2), 128, SMEM_L1>>>(lWih1, lWhh1, lb1, vWih1, vWhh1, vb1);
    head_kernel<<<256, 128>>>(dir, lfcW, lfcb, vfcW, vfcb, out);
}

// round 12
// speedup vs baseline: 1.4947x; 1.4947x over previous
#include <cuda_runtime.h>
#include <cuda_bf16.h>
#include <cuda_fp16.h>
#include <cstdint>

#define NSAMP 65536
#define BORIG 32768
#define TT    15
typedef unsigned long long u64;

__device__ u64   g_xT[(size_t)30 * NSAMP];
__device__ u64   g_l0u[(size_t)2 * TT * 32 * NSAMP];
__device__ float g_last[(size_t)2 * 64 * NSAMP];

__device__ __forceinline__ u64 pack2(float lo, float hi) {
    u64 r; asm("mov.b64 %0, {%1, %2};" : "=l"(r) : "r"(__float_as_uint(lo)), "r"(__float_as_uint(hi))); return r;
}
__device__ __forceinline__ void unpack2(u64 a, float& lo, float& hi) {
    unsigned x, y; asm("mov.b64 {%0, %1}, %2;" : "=r"(x), "=r"(y) : "l"(a));
    lo = __uint_as_float(x); hi = __uint_as_float(y);
}
__device__ __forceinline__ void fma2(u64& d, u64 a, u64 b) {
    asm("fma.rn.f32x2 %0, %1, %2, %0;" : "+l"(d) : "l"(a), "l"(b));
}
__device__ __forceinline__ float usum(u64 a) { float lo, hi; unpack2(a, lo, hi); return lo + hi; }
__device__ __forceinline__ float tanhx(float x) { float r; asm("tanh.approx.f32 %0, %1;" : "=f"(r) : "f"(x)); return r; }
__device__ __forceinline__ float sigf(float x) { return fmaf(0.5f, tanhx(0.5f * x), 0.5f); }
__device__ __forceinline__ uint32_t hpack(float lo, float hi) {   // lo -> low half (k even)
    uint32_t r; asm("cvt.rn.f16x2.f32 %0, %1, %2;" : "=r"(r) : "f"(hi), "f"(lo)); return r;
}
__device__ __forceinline__ float f16v(float x) { return __half2float(__float2half_rn(x)); }

__device__ __forceinline__ void mma16816(float* d, const uint32_t* a, const uint32_t* b) {
    asm volatile("mma.sync.aligned.m16n8k16.row.col.f32.f16.f16.f32 "
        "{%0,%1,%2,%3}, {%4,%5,%6,%7}, {%8,%9}, {%0,%1,%2,%3};"
        : "+f"(d[0]), "+f"(d[1]), "+f"(d[2]), "+f"(d[3])
        : "r"(a[0]), "r"(a[1]), "r"(a[2]), "r"(a[3]), "r"(b[0]), "r"(b[1]));
}

// ---------------- transpose (unchanged) ----------------
__global__ void __launch_bounds__(128) k_transpose(const float* __restrict__ pos)
{
    __shared__ float sx[128 * 60];
    const unsigned s0 = blockIdx.x * 128u;
    for (int idx = threadIdx.x; idx < 128 * 60; idx += 128) {
        int i = idx / 60, f = idx % 60;
        unsigned s = s0 + i;
        sx[idx] = pos[s < BORIG ? (size_t)s * 120 + f : (size_t)(s - BORIG) * 120 + 60 + f];
    }
    __syncthreads();
    const int i = threadIdx.x;
#pragma unroll
    for (int u = 0; u < 30; ++u) {
        int t = u >> 1, p = u & 1;
        g_xT[(size_t)u * NSAMP + s0 + i] = pack2(sx[i * 60 + t * 4 + p * 2], sx[i * 60 + t * 4 + p * 2 + 1]);
    }
}

// ---------------- layer0 FFMA N=4 (unchanged, proven) ----------------
__global__ void __launch_bounds__(128) lstm_layer0(
    const float* __restrict__ lWih, const float* __restrict__ lWhh, const float* __restrict__ lb,
    const float* __restrict__ vWih, const float* __restrict__ vWhh, const float* __restrict__ vb)
{
    __shared__ __align__(16) float sWf[128 * 36];
    __shared__ float sB[128];
    const int d = blockIdx.y, br = blockIdx.z;
    const float* Wih = (br ? vWih : lWih) + d * 128 * 4;
    const float* Whh = (br ? vWhh : lWhh) + d * 128 * 32;
    const float* bb  = (br ? vb   : lb  ) + d * 128;
    for (int idx = threadIdx.x; idx < 128 * 36; idx += 128) {
        int r = idx / 36, o = idx % 36;
        sWf[idx] = (o < 4) ? Wih[r * 4 + o] : Whh[r * 32 + (o - 4)];
    }
    sB[threadIdx.x] = bb[threadIdx.x];
    __syncthreads();
    const u64* sW = reinterpret_cast<const u64*>(sWf);
    const unsigned s0 = blockIdx.x * 512u + threadIdx.x;
    u64 v2[4][18];
    float c[4][32], hn[4][32];
#pragma unroll
    for (int n = 0; n < 4; ++n)
#pragma unroll
        for (int k = 2; k < 18; ++k) v2[n][k] = 0;
#pragma unroll 1
    for (int j = 0; j < 32; ++j)
#pragma unroll
        for (int n = 0; n < 4; ++n) c[n][j] = 0.f;
    for (int step = 0; step < TT; ++step) {
        const int t = d ? (TT - 1 - step) : step;
#pragma unroll
        for (int n = 0; n < 4; ++n) {
            v2[n][0] = g_xT[(size_t)(t * 2) * NSAMP + s0 + n * 128];
            v2[n][1] = g_xT[(size_t)(t * 2 + 1) * NSAMP + s0 + n * 128];
        }
#pragma unroll 1
        for (int j = 0; j < 32; ++j) {
            u64 acc[4][4];
#pragma unroll
            for (int g = 0; g < 4; ++g)
#pragma unroll
                for (int n = 0; n < 4; ++n) acc[g][n] = 0;
#pragma unroll
            for (int g = 0; g < 4; ++g) {
                const ulonglong2* row = reinterpret_cast<const ulonglong2*>(sW + (size_t)(j + 32 * g) * 18);
#pragma unroll
                for (int k2 = 0; k2 < 9; ++k2) {
                    ulonglong2 w = row[k2];
#pragma unroll
                    for (int n = 0; n < 4; ++n) {
                        fma2(acc[g][n], w.x, v2[n][2 * k2]);
                        fma2(acc[g][n], w.y, v2[n][2 * k2 + 1]);
                    }
                }
            }
            float bi = sB[j], bf = sB[j + 32], bg = sB[j + 64], bo = sB[j + 96];
#pragma unroll
            for (int n = 0; n < 4; ++n) {
                float iv = usum(acc[0][n]) + bi, fv = usum(acc[1][n]) + bf;
                float gv = usum(acc[2][n]) + bg, ov = usum(acc[3][n]) + bo;
                float cn = sigf(fv) * c[n][j] + sigf(iv) * tanhx(gv);
                c[n][j] = cn;
                hn[n][j] = sigf(ov) * tanhx(cn);
            }
        }
        u64* gb = g_l0u + ((size_t)(br * TT + t) * 32 + d * 16) * NSAMP;
#pragma unroll
        for (int q = 0; q < 16; ++q)
#pragma unroll
            for (int n = 0; n < 4; ++n) {
                u64 hp = pack2(hn[n][2 * q], hn[n][2 * q + 1]);
                v2[n][2 + q] = hp;
                gb[(size_t)q * NSAMP + s0 + n * 128] = hp;
            }
    }
}

// ---------------- layer1: mma.sync fp16 2-term, 256 threads ----------------
// A[s][k] (KPA=200): [0..63]=x_hi [64..95]=h_hi [96..159]=x_lo [160..191]=h_lo [192,193]=(1,1)
// B[r][k] (KPB=216): [0..191]=w (dup both blocks), [192]=b_hi [193]=b_lo, rest 0. 13 k-tiles.
#define SMEM_L1 ((256 * 200 + 128 * 216) * 2)

__device__ __forceinline__ void mma_main(float (&d)[2][16][4], const uint32_t* A32,
                                         const uint32_t* B32, int w, int l)
{
    const int rbase = (32 * w + (l >> 2)) * 100;
    const int kb = l & 3;
#pragma unroll 1
    for (int kt = 0; kt < 13; ++kt) {
        const int ko = kt * 8 + kb;
        uint32_t a[2][4];
#pragma unroll
        for (int mt = 0; mt < 2; ++mt) {
            int aw = rbase + mt * 1600 + ko;
            a[mt][0] = A32[aw];       a[mt][1] = A32[aw + 800];
            a[mt][2] = A32[aw + 4];   a[mt][3] = A32[aw + 804];
        }
#pragma unroll
        for (int nt = 0; nt < 16; ++nt) {
            int bw = (nt * 8 + (l >> 2)) * 108 + ko;
            uint32_t b[2] = { B32[bw], B32[bw + 4] };
            mma16816(d[0][nt], a[0], b);
            mma16816(d[1][nt], a[1], b);
        }
    }
}

__global__ void __launch_bounds__(256) mma_layer1(
    const float* __restrict__ lWih, const float* __restrict__ lWhh, const float* __restrict__ lb,
    const float* __restrict__ vWih, const float* __restrict__ vWhh, const float* __restrict__ vb)
{
    extern __shared__ __align__(16) char sm[];
    uint32_t* A32 = reinterpret_cast<uint32_t*>(sm);
    __half* Bh = reinterpret_cast<__half*>(sm + 256 * 200 * 2);
    const uint32_t* B32 = reinterpret_cast<const uint32_t*>(Bh);
    const int tid = threadIdx.x, w = tid >> 5, l = tid & 31;
    const int br = blockIdx.y;
    const unsigned s0 = blockIdx.x * 256u;
    const float* Wih = br ? vWih : lWih;
    const float* Whh = br ? vWhh : lWhh;
    const float* bbp = br ? vb : lb;

    for (int idx = tid; idx < 128 * 216; idx += 256) {        // fwd B
        int r = idx / 216, k = idx % 216;
        float wv = 0.f;
        if (k < 192)      { int kk = k % 96; wv = (kk < 64) ? Wih[r * 64 + kk] : Whh[r * 32 + kk - 64]; }
        else if (k == 192) wv = f16v(bbp[r]);
        else if (k == 193) wv = bbp[r] - f16v(bbp[r]);
        Bh[r * 216 + k] = __float2half_rn(wv);
    }
    for (int idx = tid; idx < 25600; idx += 256) A32[idx] = 0;
    __syncthreads();
    A32[tid * 100 + 96] = 0x3C003C00u;                        // k192,193 = (1.0,1.0)
    __syncthreads();

    float c[2][2][4][2];
#pragma unroll
    for (int a = 0; a < 2; ++a)
#pragma unroll
        for (int b = 0; b < 2; ++b)
#pragma unroll
            for (int g = 0; g < 4; ++g) { c[a][b][g][0] = 0.f; c[a][b][g][1] = 0.f; }

#pragma unroll 1
    for (int t = 0; t < TT; ++t) {
        const u64* gx = g_l0u + (size_t)(br * TT + t) * 32 * NSAMP + s0 + tid;
#pragma unroll
        for (int kp = 0; kp < 32; ++kp) {
            float f0, f1; unpack2(gx[(size_t)kp * NSAMP], f0, f1);
            float h0 = f16v(f0), h1 = f16v(f1);
            A32[tid * 100 + kp] = hpack(h0, h1);
            A32[tid * 100 + 48 + kp] = hpack(f0 - h0, f1 - h1);
        }
        __syncthreads();

        float d[2][16][4];
#pragma unroll
        for (int mt = 0; mt < 2; ++mt)
#pragma unroll
            for (int nt = 0; nt < 16; ++nt)
#pragma unroll
                for (int q = 0; q < 4; ++q) d[mt][nt][q] = 0.f;
        mma_main(d, A32, B32, w, l);
        __syncthreads();

#pragma unroll
        for (int mt = 0; mt < 2; ++mt)
#pragma unroll
            for (int hp = 0; hp < 2; ++hp)
#pragma unroll
                for (int g4 = 0; g4 < 4; ++g4) {
                    float hv[2];
#pragma unroll
                    for (int col = 0; col < 2; ++col) {
                        int e = hp * 2 + col;
                        float ci = d[mt][g4][e], cf = d[mt][g4 + 4][e];
                        float cg = d[mt][g4 + 8][e], co = d[mt][g4 + 12][e];
                        float cc = c[mt][hp][g4][col];
                        cc = sigf(cf) * cc + sigf(ci) * tanhx(cg);
                        c[mt][hp][g4][col] = cc;
                        hv[col] = sigf(co) * tanhx(cc);
                    }
                    int srow = 32 * w + 16 * mt + (l >> 2) + 8 * hp;
                    int jp = 8 * g4 + (l & 3) * 2;
                    if (t < TT - 1) {
                        float b0 = f16v(hv[0]), b1 = f16v(hv[1]);
                        A32[(srow * 200 + 64 + jp) >> 1]  = hpack(b0, b1);
                        A32[(srow * 200 + 160 + jp) >> 1] = hpack(hv[0] - b0, hv[1] - b1);
                    } else {
                        g_last[((size_t)br * 64 + jp) * NSAMP + s0 + srow]     = hv[0];
                        g_last[((size_t)br * 64 + jp + 1) * NSAMP + s0 + srow] = hv[1];
                    }
                }
    }
    __syncthreads();

    // rewrite B with bwd weights (h slots zero), then single bwd step on x14 (still in A)
    for (int idx = tid; idx < 128 * 216; idx += 256) {
        int r = idx / 216, k = idx % 216;
        float wv = 0.f;
        if (k < 64)                 wv = Wih[8192 + r * 64 + k];
        else if (k >= 96 && k < 160) wv = Wih[8192 + r * 64 + (k - 96)];
        else if (k == 192)          wv = f16v(bbp[128 + r]);
        else if (k == 193)          wv = bbp[128 + r] - f16v(bbp[128 + r]);
        Bh[r * 216 + k] = __float2half_rn(wv);
    }
    __syncthreads();

    float d[2][16][4];
#pragma unroll
    for (int mt = 0; mt < 2; ++mt)
#pragma unroll
        for (int nt = 0; nt < 16; ++nt)
#pragma unroll
            for (int q = 0; q < 4; ++q) d[mt][nt][q] = 0.f;
    mma_main(d, A32, B32, w, l);
#pragma unroll
    for (int mt = 0; mt < 2; ++mt)
#pragma unroll
        for (int hp = 0; hp < 2; ++hp)
#pragma unroll
            for (int g4 = 0; g4 < 4; ++g4) {
                int srow = 32 * w + 16 * mt + (l >> 2) + 8 * hp;
                int jp = 8 * g4 + (l & 3) * 2;
#pragma unroll
                for (int col = 0; col < 2; ++col) {
                    int e = hp * 2 + col;
                    float cn = sigf(d[mt][g4][e]) * tanhx(d[mt][g4 + 8][e]);   // c0 = 0
                    g_last[((size_t)br * 64 + 32 + jp + col) * NSAMP + s0 + srow] =
                        sigf(d[mt][g4 + 12][e]) * tanhx(cn);
                }
            }
}

// ---------------- head (unchanged) ----------------
__global__ void __launch_bounds__(128) head_kernel(
    const float* __restrict__ dir,
    const float* __restrict__ lW, const float* __restrict__ lbias,
    const float* __restrict__ vW, const float* __restrict__ vbias,
    float* __restrict__ out)
{
    const int b = blockIdx.x * 128 + threadIdx.x;
    if (b >= BORIG) return;
    const float* di = dir + (size_t)b * 6;
    int am = 0; float mv = di[0];
#pragma unroll
    for (int i = 1; i < 6; ++i) { float x = di[i]; if (x > mv) { mv = x; am = i; } }
    const float m_vor = (am == 1 || am == 4) ? 1.f : 0.f;
    const float m_r   = (am == 0 || am == 5) ? 1.f : 0.f;
    const float m_l   = (am == 2 || am == 3) ? 1.f : 0.f;
    const float* ll = g_last + b;
    const float* lr = g_last + b + BORIG;
    const float* vl = g_last + (size_t)64 * NSAMP + b;
    const float* vr = g_last + (size_t)64 * NSAMP + b + BORIG;
    float xr0 = lbias[0], xr1 = lbias[1], xl0 = lbias[0], xl1 = lbias[1];
#pragma unroll
    for (int k = 0; k < 64; ++k) {
        float w0 = lW[k], w1 = lW[64 + k];
        float a = lr[(size_t)k * NSAMP], bb2 = ll[(size_t)k * NSAMP];
        xr0 = fmaf(a, w0, xr0); xr1 = fmaf(a, w1, xr1);
        xl0 = fmaf(bb2, w0, xl0); xl1 = fmaf(bb2, w1, xl1);
    }
    float xv0 = vbias[0], xv1 = vbias[1];
#pragma unroll
    for (int k = 0; k < 64; ++k) {
        float a = vl[(size_t)k * NSAMP];
        xv0 = fmaf(a, vW[k], xv0); xv1 = fmaf(a, vW[128 + k], xv1);
    }
#pragma unroll
    for (int k = 0; k < 64; ++k) {
        float a = vr[(size_t)k * NSAMP];
        xv0 = fmaf(a, vW[64 + k], xv0); xv1 = fmaf(a, vW[192 + k], xv1);
    }
    out[2 * b]     = xr0 * m_r + xl0 * m_l + xv0 * m_vor;
    out[2 * b + 1] = xr1 * m_r + xl1 * m_l + xv1 * m_vor;
}

extern "C" void kernel_launch(void* const* d_in, const int* in_sizes, int n_in,
                              void* d_out, int out_size)
{
    (void)in_sizes; (void)n_in; (void)out_size;
    const float* dir   = (const float*)d_in[0];
    const float* pos   = (const float*)d_in[1];
    const float* lWih0 = (const float*)d_in[2];
    const float* lWhh0 = (const float*)d_in[3];
    const float* lb0   = (const float*)d_in[4];
    const float* lWih1 = (const float*)d_in[5];
    const float* lWhh1 = (const float*)d_in[6];
    const float* lb1   = (const float*)d_in[7];
    const float* vWih0 = (const float*)d_in[8];
    const float* vWhh0 = (const float*)d_in[9];
    const float* vb0   = (const float*)d_in[10];
    const float* vWih1 = (const float*)d_in[11];
    const float* vWhh1 = (const float*)d_in[12];
    const float* vb1   = (const float*)d_in[13];
    const float* lfcW  = (const float*)d_in[14];
    const float* lfcb  = (const float*)d_in[15];
    const float* vfcW  = (const float*)d_in[16];
    const float* vfcb  = (const float*)d_in[17];
    float* out = (float*)d_out;

    cudaFuncSetAttribute(mma_layer1, cudaFuncAttributeMaxDynamicSharedMemorySize, SMEM_L1);

    k_transpose<<<NSAMP / 128, 128>>>(pos);
    lstm_layer0<<<dim3(NSAMP / 512, 2, 2), 128>>>(lWih0, lWhh0, lb0, vWih0, vWhh0, vb0);
    mma_layer1<<<dim3(NSAMP / 256, 2), 256, SMEM_L1>>>(lWih1, lWhh1, lb1, vWih1, vWhh1, vb1);
    head_kernel<<<256, 128>>>(dir, lfcW, lfcb, vfcW, vfcb, out);
}

// round 13
// speedup vs baseline: 1.7609x; 1.1781x over previous
#include <cuda_runtime.h>
#include <cuda_fp16.h>
#include <cstdint>

#define NSAMP 65536
#define BORIG 32768
#define TT    15
typedef unsigned long long u64;

__device__ u64   g_xT[(size_t)30 * NSAMP];
__device__ u64   g_l0u[(size_t)2 * TT * 32 * NSAMP];
__device__ float g_last[(size_t)2 * 64 * NSAMP];

__device__ __forceinline__ u64 pack2(float lo, float hi) {
    u64 r; asm("mov.b64 %0, {%1, %2};" : "=l"(r) : "r"(__float_as_uint(lo)), "r"(__float_as_uint(hi))); return r;
}
__device__ __forceinline__ void unpack2(u64 a, float& lo, float& hi) {
    unsigned x, y; asm("mov.b64 {%0, %1}, %2;" : "=r"(x), "=r"(y) : "l"(a));
    lo = __uint_as_float(x); hi = __uint_as_float(y);
}
__device__ __forceinline__ float tanhx(float x) { float r; asm("tanh.approx.f32 %0, %1;" : "=f"(r) : "f"(x)); return r; }
__device__ __forceinline__ float sigf(float x) { return fmaf(0.5f, tanhx(0.5f * x), 0.5f); }
__device__ __forceinline__ uint32_t hpack(float lo, float hi) {
    uint32_t r; asm("cvt.rn.f16x2.f32 %0, %1, %2;" : "=r"(r) : "f"(hi), "f"(lo)); return r;
}
__device__ __forceinline__ float f16v(float x) { return __half2float(__float2half_rn(x)); }

__device__ __forceinline__ void mma16816(float* d, const uint32_t* a, const uint32_t* b) {
    asm volatile("mma.sync.aligned.m16n8k16.row.col.f32.f16.f16.f32 "
        "{%0,%1,%2,%3}, {%4,%5,%6,%7}, {%8,%9}, {%0,%1,%2,%3};"
        : "+f"(d[0]), "+f"(d[1]), "+f"(d[2]), "+f"(d[3])
        : "r"(a[0]), "r"(a[1]), "r"(a[2]), "r"(a[3]), "r"(b[0]), "r"(b[1]));
}

// Shared HMMA mainloop: 128 samples (4 warps, 2 m-tiles each) x 128 gates x NKT k-tiles.
template<int NKT, int KPAW, int KPBW>
__device__ __forceinline__ void mma_main(float (&d)[2][16][4], const uint32_t* A32,
                                         const uint32_t* B32, int w, int l)
{
    const int r0 = 32 * w + (l >> 2);
    const int kb = l & 3;
#pragma unroll 1
    for (int kt = 0; kt < NKT; ++kt) {
        const int ko = kt * 8 + kb;
        uint32_t a[2][4];
#pragma unroll
        for (int mt = 0; mt < 2; ++mt) {
            int aw = (r0 + 16 * mt) * KPAW + ko;
            a[mt][0] = A32[aw];     a[mt][1] = A32[aw + 8 * KPAW];
            a[mt][2] = A32[aw + 4]; a[mt][3] = A32[aw + 8 * KPAW + 4];
        }
#pragma unroll
        for (int nt = 0; nt < 16; ++nt) {
            int bw = (nt * 8 + (l >> 2)) * KPBW + ko;
            uint32_t b[2] = { B32[bw], B32[bw + 4] };
            mma16816(d[0][nt], a[0], b);
            mma16816(d[1][nt], a[1], b);
        }
    }
}

// ---------------- transpose ----------------
__global__ void __launch_bounds__(128) k_transpose(const float* __restrict__ pos)
{
    __shared__ float sx[128 * 60];
    const unsigned s0 = blockIdx.x * 128u;
    for (int idx = threadIdx.x; idx < 128 * 60; idx += 128) {
        int i = idx / 60, f = idx % 60;
        unsigned s = s0 + i;
        sx[idx] = pos[s < BORIG ? (size_t)s * 120 + f : (size_t)(s - BORIG) * 120 + 60 + f];
    }
    __syncthreads();
    const int i = threadIdx.x;
#pragma unroll
    for (int u = 0; u < 30; ++u) {
        int t = u >> 1, p = u & 1;
        g_xT[(size_t)u * NSAMP + s0 + i] = pack2(sx[i * 60 + t * 4 + p * 2], sx[i * 60 + t * 4 + p * 2 + 1]);
    }
}

// ---------------- layer0: HMMA fp16 2-term. K: [x_hi 0..3|h_hi 4..35|x_lo 36..39|h_lo 40..71|bias 72,73] 5kt
#define SMEM_L0 ((128 * 84 + 128 * 88) * 2)
__global__ void __launch_bounds__(128, 2) mma_layer0(
    const float* __restrict__ lWih, const float* __restrict__ lWhh, const float* __restrict__ lb,
    const float* __restrict__ vWih, const float* __restrict__ vWhh, const float* __restrict__ vb)
{
    extern __shared__ __align__(16) char sm0[];
    uint32_t* A32 = reinterpret_cast<uint32_t*>(sm0);
    __half* Bh = reinterpret_cast<__half*>(sm0 + 128 * 84 * 2);
    const uint32_t* B32 = reinterpret_cast<const uint32_t*>(Bh);
    const int tid = threadIdx.x, w = tid >> 5, l = tid & 31;
    const int br = blockIdx.y, dd = blockIdx.z;
    const unsigned s0 = blockIdx.x * 128u;
    const float* Wih = (br ? vWih : lWih) + dd * 128 * 4;
    const float* Whh = (br ? vWhh : lWhh) + dd * 128 * 32;
    const float* bbp = (br ? vb   : lb  ) + dd * 128;

    for (int idx = tid; idx < 128 * 88; idx += 128) {
        int r = idx / 88, k = idx % 88;
        float wv = 0.f;
        if (k < 72)       { int kk = k % 36; wv = (kk < 4) ? Wih[r * 4 + kk] : Whh[r * 32 + kk - 4]; }
        else if (k == 72)  wv = f16v(bbp[r]);
        else if (k == 73)  wv = bbp[r] - f16v(bbp[r]);
        Bh[r * 88 + k] = __float2half_rn(wv);
    }
    for (int idx = tid; idx < 128 * 42; idx += 128) A32[idx] = 0;
    __syncthreads();
    A32[tid * 42 + 36] = 0x3C003C00u;                        // bias lanes (1,1)
    __syncthreads();

    float c[2][2][4][2];
#pragma unroll
    for (int a = 0; a < 2; ++a)
#pragma unroll
        for (int b = 0; b < 2; ++b)
#pragma unroll
            for (int g = 0; g < 4; ++g) { c[a][b][g][0] = 0.f; c[a][b][g][1] = 0.f; }

#pragma unroll 1
    for (int step = 0; step < TT; ++step) {
        const int t = dd ? (TT - 1 - step) : step;
        {
            float f0, f1, f2, f3;
            unpack2(g_xT[(size_t)(2 * t) * NSAMP + s0 + tid], f0, f1);
            unpack2(g_xT[(size_t)(2 * t + 1) * NSAMP + s0 + tid], f2, f3);
            float h0 = f16v(f0), h1 = f16v(f1), h2 = f16v(f2), h3 = f16v(f3);
            A32[tid * 42]      = hpack(h0, h1);
            A32[tid * 42 + 1]  = hpack(h2, h3);
            A32[tid * 42 + 18] = hpack(f0 - h0, f1 - h1);
            A32[tid * 42 + 19] = hpack(f2 - h2, f3 - h3);
        }
        __syncthreads();

        float d[2][16][4];
#pragma unroll
        for (int mt = 0; mt < 2; ++mt)
#pragma unroll
            for (int nt = 0; nt < 16; ++nt)
#pragma unroll
                for (int q = 0; q < 4; ++q) d[mt][nt][q] = 0.f;
        mma_main<5, 42, 44>(d, A32, B32, w, l);
        __syncthreads();

#pragma unroll
        for (int mt = 0; mt < 2; ++mt)
#pragma unroll
            for (int hp = 0; hp < 2; ++hp)
#pragma unroll
                for (int g4 = 0; g4 < 4; ++g4) {
                    float hv[2];
#pragma unroll
                    for (int col = 0; col < 2; ++col) {
                        int e = hp * 2 + col;
                        float cc = c[mt][hp][g4][col];
                        cc = sigf(d[mt][g4 + 4][e]) * cc + sigf(d[mt][g4][e]) * tanhx(d[mt][g4 + 8][e]);
                        c[mt][hp][g4][col] = cc;
                        hv[col] = sigf(d[mt][g4 + 12][e]) * tanhx(cc);
                    }
                    int srow = 32 * w + 16 * mt + (l >> 2) + 8 * hp;
                    int jp = 8 * g4 + (l & 3) * 2;
                    g_l0u[((size_t)(br * TT + t) * 32 + dd * 16 + (jp >> 1)) * NSAMP + s0 + srow] =
                        pack2(hv[0], hv[1]);
                    if (step < TT - 1) {
                        float b0 = f16v(hv[0]), b1 = f16v(hv[1]);
                        A32[srow * 42 + 2 + (jp >> 1)]  = hpack(b0, b1);
                        A32[srow * 42 + 20 + (jp >> 1)] = hpack(hv[0] - b0, hv[1] - b1);
                    }
                }
    }
}

// ---------------- layer1: HMMA fp16 2-term, 128 threads (2 CTA/SM) ----------------
// A (KPA=200 halves): [0..63]=x_hi [64..95]=h_hi [96..159]=x_lo [160..191]=h_lo [192,193]=(1,1)
// B (KPB=216 halves): [0..191]=w dup, [192]=b_hi [193]=b_lo. 13 k-tiles.
#define SMEM_L1 ((128 * 200 + 128 * 216) * 2)
__global__ void __launch_bounds__(128, 2) mma_layer1(
    const float* __restrict__ lWih, const float* __restrict__ lWhh, const float* __restrict__ lb,
    const float* __restrict__ vWih, const float* __restrict__ vWhh, const float* __restrict__ vb)
{
    extern __shared__ __align__(16) char sm[];
    uint32_t* A32 = reinterpret_cast<uint32_t*>(sm);
    __half* Bh = reinterpret_cast<__half*>(sm + 128 * 200 * 2);
    const uint32_t* B32 = reinterpret_cast<const uint32_t*>(Bh);
    const int tid = threadIdx.x, w = tid >> 5, l = tid & 31;
    const int br = blockIdx.y;
    const unsigned s0 = blockIdx.x * 128u;
    const float* Wih = br ? vWih : lWih;
    const float* Whh = br ? vWhh : lWhh;
    const float* bbp = br ? vb : lb;

    for (int idx = tid; idx < 128 * 216; idx += 128) {
        int r = idx / 216, k = idx % 216;
        float wv = 0.f;
        if (k < 192)      { int kk = k % 96; wv = (kk < 64) ? Wih[r * 64 + kk] : Whh[r * 32 + kk - 64]; }
        else if (k == 192) wv = f16v(bbp[r]);
        else if (k == 193) wv = bbp[r] - f16v(bbp[r]);
        Bh[r * 216 + k] = __float2half_rn(wv);
    }
    for (int idx = tid; idx < 12800; idx += 128) A32[idx] = 0;
    __syncthreads();
    A32[tid * 100 + 96] = 0x3C003C00u;
    __syncthreads();

    float c[2][2][4][2];
#pragma unroll
    for (int a = 0; a < 2; ++a)
#pragma unroll
        for (int b = 0; b < 2; ++b)
#pragma unroll
            for (int g = 0; g < 4; ++g) { c[a][b][g][0] = 0.f; c[a][b][g][1] = 0.f; }

#pragma unroll 1
    for (int t = 0; t < TT; ++t) {
        const u64* gx = g_l0u + (size_t)(br * TT + t) * 32 * NSAMP + s0 + tid;
#pragma unroll
        for (int kp = 0; kp < 32; ++kp) {
            float f0, f1; unpack2(gx[(size_t)kp * NSAMP], f0, f1);
            float h0 = f16v(f0), h1 = f16v(f1);
            A32[tid * 100 + kp] = hpack(h0, h1);
            A32[tid * 100 + 48 + kp] = hpack(f0 - h0, f1 - h1);
        }
        __syncthreads();

        float d[2][16][4];
#pragma unroll
        for (int mt = 0; mt < 2; ++mt)
#pragma unroll
            for (int nt = 0; nt < 16; ++nt)
#pragma unroll
                for (int q = 0; q < 4; ++q) d[mt][nt][q] = 0.f;
        mma_main<13, 100, 108>(d, A32, B32, w, l);
        __syncthreads();

#pragma unroll
        for (int mt = 0; mt < 2; ++mt)
#pragma unroll
            for (int hp = 0; hp < 2; ++hp)
#pragma unroll
                for (int g4 = 0; g4 < 4; ++g4) {
                    float hv[2];
#pragma unroll
                    for (int col = 0; col < 2; ++col) {
                        int e = hp * 2 + col;
                        float cc = c[mt][hp][g4][col];
                        cc = sigf(d[mt][g4 + 4][e]) * cc + sigf(d[mt][g4][e]) * tanhx(d[mt][g4 + 8][e]);
                        c[mt][hp][g4][col] = cc;
                        hv[col] = sigf(d[mt][g4 + 12][e]) * tanhx(cc);
                    }
                    int srow = 32 * w + 16 * mt + (l >> 2) + 8 * hp;
                    int jp = 8 * g4 + (l & 3) * 2;
                    if (t < TT - 1) {
                        float b0 = f16v(hv[0]), b1 = f16v(hv[1]);
                        A32[srow * 100 + 32 + (jp >> 1)] = hpack(b0, b1);
                        A32[srow * 100 + 80 + (jp >> 1)] = hpack(hv[0] - b0, hv[1] - b1);
                    } else {
                        g_last[((size_t)br * 64 + jp) * NSAMP + s0 + srow]     = hv[0];
                        g_last[((size_t)br * 64 + jp + 1) * NSAMP + s0 + srow] = hv[1];
                    }
                }
    }
    __syncthreads();

    // rewrite B with bwd weights (h slots zero), single bwd step on x14 (still staged in A)
    for (int idx = tid; idx < 128 * 216; idx += 128) {
        int r = idx / 216, k = idx % 216;
        float wv = 0.f;
        if (k < 64)                  wv = Wih[8192 + r * 64 + k];
        else if (k >= 96 && k < 160) wv = Wih[8192 + r * 64 + (k - 96)];
        else if (k == 192)           wv = f16v(bbp[128 + r]);
        else if (k == 193)           wv = bbp[128 + r] - f16v(bbp[128 + r]);
        Bh[r * 216 + k] = __float2half_rn(wv);
    }
    __syncthreads();

    float d[2][16][4];
#pragma unroll
    for (int mt = 0; mt < 2; ++mt)
#pragma unroll
        for (int nt = 0; nt < 16; ++nt)
#pragma unroll
            for (int q = 0; q < 4; ++q) d[mt][nt][q] = 0.f;
    mma_main<13, 100, 108>(d, A32, B32, w, l);
#pragma unroll
    for (int mt = 0; mt < 2; ++mt)
#pragma unroll
        for (int hp = 0; hp < 2; ++hp)
#pragma unroll
            for (int g4 = 0; g4 < 4; ++g4) {
                int srow = 32 * w + 16 * mt + (l >> 2) + 8 * hp;
                int jp = 8 * g4 + (l & 3) * 2;
#pragma unroll
                for (int col = 0; col < 2; ++col) {
                    int e = hp * 2 + col;
                    float cn = sigf(d[mt][g4][e]) * tanhx(d[mt][g4 + 8][e]);   // c0 = 0
                    g_last[((size_t)br * 64 + 32 + jp + col) * NSAMP + s0 + srow] =
                        sigf(d[mt][g4 + 12][e]) * tanhx(cn);
                }
            }
}

// ---------------- head ----------------
__global__ void __launch_bounds__(128) head_kernel(
    const float* __restrict__ dir,
    const float* __restrict__ lW, const float* __restrict__ lbias,
    const float* __restrict__ vW, const float* __restrict__ vbias,
    float* __restrict__ out)
{
    const int b = blockIdx.x * 128 + threadIdx.x;
    if (b >= BORIG) return;
    const float* di = dir + (size_t)b * 6;
    int am = 0; float mv = di[0];
#pragma unroll
    for (int i = 1; i < 6; ++i) { float x = di[i]; if (x > mv) { mv = x; am = i; } }
    const float m_vor = (am == 1 || am == 4) ? 1.f : 0.f;
    const float m_r   = (am == 0 || am == 5) ? 1.f : 0.f;
    const float m_l   = (am == 2 || am == 3) ? 1.f : 0.f;
    const float* ll = g_last + b;
    const float* lr = g_last + b + BORIG;
    const float* vl = g_last + (size_t)64 * NSAMP + b;
    const float* vr = g_last + (size_t)64 * NSAMP + b + BORIG;
    float xr0 = lbias[0], xr1 = lbias[1], xl0 = lbias[0], xl1 = lbias[1];
#pragma unroll
    for (int k = 0; k < 64; ++k) {
        float w0 = lW[k], w1 = lW[64 + k];
        float a = lr[(size_t)k * NSAMP], bb2 = ll[(size_t)k * NSAMP];
        xr0 = fmaf(a, w0, xr0); xr1 = fmaf(a, w1, xr1);
        xl0 = fmaf(bb2, w0, xl0); xl1 = fmaf(bb2, w1, xl1);
    }
    float xv0 = vbias[0], xv1 = vbias[1];
#pragma unroll
    for (int k = 0; k < 64; ++k) {
        float a = vl[(size_t)k * NSAMP];
        xv0 = fmaf(a, vW[k], xv0); xv1 = fmaf(a, vW[128 + k], xv1);
    }
#pragma unroll
    for (int k = 0; k < 64; ++k) {
        float a = vr[(size_t)k * NSAMP];
        xv0 = fmaf(a, vW[64 + k], xv0); xv1 = fmaf(a, vW[192 + k], xv1);
    }
    out[2 * b]     = xr0 * m_r + xl0 * m_l + xv0 * m_vor;
    out[2 * b + 1] = xr1 * m_r + xl1 * m_l + xv1 * m_vor;
}

extern "C" void kernel_launch(void* const* d_in, const int* in_sizes, int n_in,
                              void* d_out, int out_size)
{
    (void)in_sizes; (void)n_in; (void)out_size;
    const float* dir   = (const float*)d_in[0];
    const float* pos   = (const float*)d_in[1];
    const float* lWih0 = (const float*)d_in[2];
    const float* lWhh0 = (const float*)d_in[3];
    const float* lb0   = (const float*)d_in[4];
    const float* lWih1 = (const float*)d_in[5];
    const float* lWhh1 = (const float*)d_in[6];
    const float* lb1   = (const float*)d_in[7];
    const float* vWih0 = (const float*)d_in[8];
    const float* vWhh0 = (const float*)d_in[9];
    const float* vb0   = (const float*)d_in[10];
    const float* vWih1 = (const float*)d_in[11];
    const float* vWhh1 = (const float*)d_in[12];
    const float* vb1   = (const float*)d_in[13];
    const float* lfcW  = (const float*)d_in[14];
    const float* lfcb  = (const float*)d_in[15];
    const float* vfcW  = (const float*)d_in[16];
    const float* vfcb  = (const float*)d_in[17];
    float* out = (float*)d_out;

    cudaFuncSetAttribute(mma_layer0, cudaFuncAttributeMaxDynamicSharedMemorySize, SMEM_L0);
    cudaFuncSetAttribute(mma_layer1, cudaFuncAttributeMaxDynamicSharedMemorySize, SMEM_L1);

    k_transpose<<<NSAMP / 128, 128>>>(pos);
    mma_layer0<<<dim3(NSAMP / 128, 2, 2), 128, SMEM_L0>>>(lWih0, lWhh0, lb0, vWih0, vWhh0, vb0);
    mma_layer1<<<dim3(NSAMP / 128, 2), 128, SMEM_L1>>>(lWih1, lWhh1, lb1, vWih1, vWhh1, vb1);
    head_kernel<<<256, 128>>>(dir, lfcW, lfcb, vfcW, vfcb, out);
}

// round 14
// speedup vs baseline: 2.5751x; 1.4624x over previous
#include <cuda_runtime.h>
#include <cuda_fp16.h>
#include <cstdint>

#define NSAMP 65536
#define BORIG 32768
#define TT    15
typedef unsigned long long u64;

__device__ u64   g_xT[(size_t)30 * NSAMP];
__device__ u64   g_l0u[(size_t)2 * TT * 32 * NSAMP];
__device__ float g_last[(size_t)2 * 64 * NSAMP];

__device__ __forceinline__ u64 pack2(float lo, float hi) {
    u64 r; asm("mov.b64 %0, {%1, %2};" : "=l"(r) : "r"(__float_as_uint(lo)), "r"(__float_as_uint(hi))); return r;
}
__device__ __forceinline__ void unpack2(u64 a, float& lo, float& hi) {
    unsigned x, y; asm("mov.b64 {%0, %1}, %2;" : "=r"(x), "=r"(y) : "l"(a));
    lo = __uint_as_float(x); hi = __uint_as_float(y);
}
__device__ __forceinline__ float tanhx(float x) { float r; asm("tanh.approx.f32 %0, %1;" : "=f"(r) : "f"(x)); return r; }
__device__ __forceinline__ float sigf(float x) { return fmaf(0.5f, tanhx(0.5f * x), 0.5f); }
__device__ __forceinline__ uint32_t hpack(float lo, float hi) {
    uint32_t r; asm("cvt.rn.f16x2.f32 %0, %1, %2;" : "=r"(r) : "f"(hi), "f"(lo)); return r;
}
__device__ __forceinline__ float f16v(float x) { return __half2float(__float2half_rn(x)); }

__device__ __forceinline__ void mma16816(float* d, const uint32_t* a, const uint32_t* b) {
    asm volatile("mma.sync.aligned.m16n8k16.row.col.f32.f16.f16.f32 "
        "{%0,%1,%2,%3}, {%4,%5,%6,%7}, {%8,%9}, {%0,%1,%2,%3};"
        : "+f"(d[0]), "+f"(d[1]), "+f"(d[2]), "+f"(d[3])
        : "r"(a[0]), "r"(a[1]), "r"(a[2]), "r"(a[3]), "r"(b[0]), "r"(b[1]));
}

// HMMA mainloop: 128 samples (4 warps x 2 m-tiles) x 128 gates x NKT k-tiles.
// KPAW/KPBW are word strides, both ≡ 28 (mod 32) -> conflict-free fragment loads.
template<int NKT, int KPAW, int KPBW>
__device__ __forceinline__ void mma_main(float (&d)[2][16][4], const uint32_t* A32,
                                         const uint32_t* B32, int w, int l)
{
    const int r0 = 32 * w + (l >> 2);
    const int kb = l & 3;
#pragma unroll 1
    for (int kt = 0; kt < NKT; ++kt) {
        const int ko = kt * 8 + kb;
        uint32_t a[2][4];
#pragma unroll
        for (int mt = 0; mt < 2; ++mt) {
            int aw = (r0 + 16 * mt) * KPAW + ko;
            a[mt][0] = A32[aw];     a[mt][1] = A32[aw + 8 * KPAW];
            a[mt][2] = A32[aw + 4]; a[mt][3] = A32[aw + 8 * KPAW + 4];
        }
#pragma unroll
        for (int nt = 0; nt < 16; ++nt) {
            int bw = (nt * 8 + (l >> 2)) * KPBW + ko;
            uint32_t b[2] = { B32[bw], B32[bw + 4] };
            mma16816(d[0][nt], a[0], b);
            mma16816(d[1][nt], a[1], b);
        }
    }
}

// ---------------- transpose ----------------
__global__ void __launch_bounds__(128) k_transpose(const float* __restrict__ pos)
{
    __shared__ float sx[128 * 60];
    const unsigned s0 = blockIdx.x * 128u;
    for (int idx = threadIdx.x; idx < 128 * 60; idx += 128) {
        int i = idx / 60, f = idx % 60;
        unsigned s = s0 + i;
        sx[idx] = pos[s < BORIG ? (size_t)s * 120 + f : (size_t)(s - BORIG) * 120 + 60 + f];
    }
    __syncthreads();
    const int i = threadIdx.x;
#pragma unroll
    for (int u = 0; u < 30; ++u) {
        int t = u >> 1, p = u & 1;
        g_xT[(size_t)u * NSAMP + s0 + i] = pack2(sx[i * 60 + t * 4 + p * 2], sx[i * 60 + t * 4 + p * 2 + 1]);
    }
}

// ---------------- layer0: fp16 activations. K halves: [x 0..3 | h 4..35 | bias 36,37] -> 3 k-tiles
// KPA = KPB = 28 words (56 halves)
#define SMEM_L0 ((128 * 28 + 128 * 28) * 4)
__global__ void __launch_bounds__(128, 2) mma_layer0(
    const float* __restrict__ lWih, const float* __restrict__ lWhh, const float* __restrict__ lb,
    const float* __restrict__ vWih, const float* __restrict__ vWhh, const float* __restrict__ vb)
{
    extern __shared__ __align__(16) char sm0[];
    uint32_t* A32 = reinterpret_cast<uint32_t*>(sm0);
    __half* Bh = reinterpret_cast<__half*>(sm0 + 128 * 28 * 4);
    const uint32_t* B32 = reinterpret_cast<const uint32_t*>(Bh);
    const int tid = threadIdx.x, w = tid >> 5, l = tid & 31;
    const int br = blockIdx.y, dd = blockIdx.z;
    const unsigned s0 = blockIdx.x * 128u;
    const float* Wih = (br ? vWih : lWih) + dd * 128 * 4;
    const float* Whh = (br ? vWhh : lWhh) + dd * 128 * 32;
    const float* bbp = (br ? vb   : lb  ) + dd * 128;

    for (int idx = tid; idx < 128 * 56; idx += 128) {
        int r = idx / 56, k = idx % 56;
        float wv = 0.f;
        if (k < 36)        wv = (k < 4) ? Wih[r * 4 + k] : Whh[r * 32 + k - 4];
        else if (k == 36)  wv = f16v(bbp[r]);
        else if (k == 37)  wv = bbp[r] - f16v(bbp[r]);
        Bh[r * 56 + k] = __float2half_rn(wv);
    }
    for (int idx = tid; idx < 128 * 28; idx += 128) A32[idx] = 0;
    __syncthreads();
    A32[tid * 28 + 18] = 0x3C003C00u;                        // bias lanes (1,1)
    __syncthreads();

    float c[2][2][4][2];
#pragma unroll
    for (int a = 0; a < 2; ++a)
#pragma unroll
        for (int b = 0; b < 2; ++b)
#pragma unroll
            for (int g = 0; g < 4; ++g) { c[a][b][g][0] = 0.f; c[a][b][g][1] = 0.f; }

#pragma unroll 1
    for (int step = 0; step < TT; ++step) {
        const int t = dd ? (TT - 1 - step) : step;
        {
            float f0, f1, f2, f3;
            unpack2(g_xT[(size_t)(2 * t) * NSAMP + s0 + tid], f0, f1);
            unpack2(g_xT[(size_t)(2 * t + 1) * NSAMP + s0 + tid], f2, f3);
            A32[tid * 28]     = hpack(f0, f1);
            A32[tid * 28 + 1] = hpack(f2, f3);
        }
        __syncthreads();

        float d[2][16][4];
#pragma unroll
        for (int mt = 0; mt < 2; ++mt)
#pragma unroll
            for (int nt = 0; nt < 16; ++nt)
#pragma unroll
                for (int q = 0; q < 4; ++q) d[mt][nt][q] = 0.f;
        mma_main<3, 28, 28>(d, A32, B32, w, l);
        __syncthreads();

#pragma unroll
        for (int mt = 0; mt < 2; ++mt)
#pragma unroll
            for (int hp = 0; hp < 2; ++hp)
#pragma unroll
                for (int g4 = 0; g4 < 4; ++g4) {
                    float hv[2];
#pragma unroll
                    for (int col = 0; col < 2; ++col) {
                        int e = hp * 2 + col;
                        float cc = c[mt][hp][g4][col];
                        cc = sigf(d[mt][g4 + 4][e]) * cc + sigf(d[mt][g4][e]) * tanhx(d[mt][g4 + 8][e]);
                        c[mt][hp][g4][col] = cc;
                        hv[col] = sigf(d[mt][g4 + 12][e]) * tanhx(cc);
                    }
                    int srow = 32 * w + 16 * mt + (l >> 2) + 8 * hp;
                    int jp = 8 * g4 + (l & 3) * 2;
                    g_l0u[((size_t)(br * TT + t) * 32 + dd * 16 + (jp >> 1)) * NSAMP + s0 + srow] =
                        pack2(hv[0], hv[1]);
                    if (step < TT - 1)
                        A32[srow * 28 + 2 + (jp >> 1)] = hpack(hv[0], hv[1]);
                }
    }
}

// ---------------- layer1: fp16 activations. K halves: [x 0..63 | h 64..95 | bias 96,97] -> 7 k-tiles
// KPA = KPB = 60 words (120 halves)
#define SMEM_L1 ((128 * 60 + 128 * 60) * 4)
__global__ void __launch_bounds__(128, 2) mma_layer1(
    const float* __restrict__ lWih, const float* __restrict__ lWhh, const float* __restrict__ lb,
    const float* __restrict__ vWih, const float* __restrict__ vWhh, const float* __restrict__ vb)
{
    extern __shared__ __align__(16) char sm[];
    uint32_t* A32 = reinterpret_cast<uint32_t*>(sm);
    __half* Bh = reinterpret_cast<__half*>(sm + 128 * 60 * 4);
    const uint32_t* B32 = reinterpret_cast<const uint32_t*>(Bh);
    const int tid = threadIdx.x, w = tid >> 5, l = tid & 31;
    const int br = blockIdx.y;
    const unsigned s0 = blockIdx.x * 128u;
    const float* Wih = br ? vWih : lWih;
    const float* Whh = br ? vWhh : lWhh;
    const float* bbp = br ? vb : lb;

    for (int idx = tid; idx < 128 * 120; idx += 128) {
        int r = idx / 120, k = idx % 120;
        float wv = 0.f;
        if (k < 96)        wv = (k < 64) ? Wih[r * 64 + k] : Whh[r * 32 + k - 64];
        else if (k == 96)  wv = f16v(bbp[r]);
        else if (k == 97)  wv = bbp[r] - f16v(bbp[r]);
        Bh[r * 120 + k] = __float2half_rn(wv);
    }
    for (int idx = tid; idx < 128 * 60; idx += 128) A32[idx] = 0;
    __syncthreads();
    A32[tid * 60 + 48] = 0x3C003C00u;                        // bias lanes (1,1)
    __syncthreads();

    float c[2][2][4][2];
#pragma unroll
    for (int a = 0; a < 2; ++a)
#pragma unroll
        for (int b = 0; b < 2; ++b)
#pragma unroll
            for (int g = 0; g < 4; ++g) { c[a][b][g][0] = 0.f; c[a][b][g][1] = 0.f; }

#pragma unroll 1
    for (int t = 0; t < TT; ++t) {
        const u64* gx = g_l0u + (size_t)(br * TT + t) * 32 * NSAMP + s0 + tid;
#pragma unroll
        for (int kp = 0; kp < 32; ++kp) {
            float f0, f1; unpack2(gx[(size_t)kp * NSAMP], f0, f1);
            A32[tid * 60 + kp] = hpack(f0, f1);
        }
        __syncthreads();

        float d[2][16][4];
#pragma unroll
        for (int mt = 0; mt < 2; ++mt)
#pragma unroll
            for (int nt = 0; nt < 16; ++nt)
#pragma unroll
                for (int q = 0; q < 4; ++q) d[mt][nt][q] = 0.f;
        mma_main<7, 60, 60>(d, A32, B32, w, l);
        __syncthreads();

#pragma unroll
        for (int mt = 0; mt < 2; ++mt)
#pragma unroll
            for (int hp = 0; hp < 2; ++hp)
#pragma unroll
                for (int g4 = 0; g4 < 4; ++g4) {
                    float hv[2];
#pragma unroll
                    for (int col = 0; col < 2; ++col) {
                        int e = hp * 2 + col;
                        float cc = c[mt][hp][g4][col];
                        cc = sigf(d[mt][g4 + 4][e]) * cc + sigf(d[mt][g4][e]) * tanhx(d[mt][g4 + 8][e]);
                        c[mt][hp][g4][col] = cc;
                        hv[col] = sigf(d[mt][g4 + 12][e]) * tanhx(cc);
                    }
                    int srow = 32 * w + 16 * mt + (l >> 2) + 8 * hp;
                    int jp = 8 * g4 + (l & 3) * 2;
                    if (t < TT - 1) {
                        A32[srow * 60 + 32 + (jp >> 1)] = hpack(hv[0], hv[1]);
                    } else {
                        g_last[((size_t)br * 64 + jp) * NSAMP + s0 + srow]     = hv[0];
                        g_last[((size_t)br * 64 + jp + 1) * NSAMP + s0 + srow] = hv[1];
                    }
                }
    }
    __syncthreads();

    // rewrite B with bwd weights (h slots zero), single bwd step on x14 (still staged in A)
    for (int idx = tid; idx < 128 * 120; idx += 128) {
        int r = idx / 120, k = idx % 120;
        float wv = 0.f;
        if (k < 64)        wv = Wih[8192 + r * 64 + k];
        else if (k == 96)  wv = f16v(bbp[128 + r]);
        else if (k == 97)  wv = bbp[128 + r] - f16v(bbp[128 + r]);
        Bh[r * 120 + k] = __float2half_rn(wv);
    }
    __syncthreads();

    float d[2][16][4];
#pragma unroll
    for (int mt = 0; mt < 2; ++mt)
#pragma unroll
        for (int nt = 0; nt < 16; ++nt)
#pragma unroll
            for (int q = 0; q < 4; ++q) d[mt][nt][q] = 0.f;
    mma_main<7, 60, 60>(d, A32, B32, w, l);
#pragma unroll
    for (int mt = 0; mt < 2; ++mt)
#pragma unroll
        for (int hp = 0; hp < 2; ++hp)
#pragma unroll
            for (int g4 = 0; g4 < 4; ++g4) {
                int srow = 32 * w + 16 * mt + (l >> 2) + 8 * hp;
                int jp = 8 * g4 + (l & 3) * 2;
#pragma unroll
                for (int col = 0; col < 2; ++col) {
                    int e = hp * 2 + col;
                    float cn = sigf(d[mt][g4][e]) * tanhx(d[mt][g4 + 8][e]);   // c0 = 0
                    g_last[((size_t)br * 64 + 32 + jp + col) * NSAMP + s0 + srow] =
                        sigf(d[mt][g4 + 12][e]) * tanhx(cn);
                }
            }
}

// ---------------- head ----------------
__global__ void __launch_bounds__(128) head_kernel(
    const float* __restrict__ dir,
    const float* __restrict__ lW, const float* __restrict__ lbias,
    const float* __restrict__ vW, const float* __restrict__ vbias,
    float* __restrict__ out)
{
    const int b = blockIdx.x * 128 + threadIdx.x;
    if (b >= BORIG) return;
    const float* di = dir + (size_t)b * 6;
    int am = 0; float mv = di[0];
#pragma unroll
    for (int i = 1; i < 6; ++i) { float x = di[i]; if (x > mv) { mv = x; am = i; } }
    const float m_vor = (am == 1 || am == 4) ? 1.f : 0.f;
    const float m_r   = (am == 0 || am == 5) ? 1.f : 0.f;
    const float m_l   = (am == 2 || am == 3) ? 1.f : 0.f;
    const float* ll = g_last + b;
    const float* lr = g_last + b + BORIG;
    const float* vl = g_last + (size_t)64 * NSAMP + b;
    const float* vr = g_last + (size_t)64 * NSAMP + b + BORIG;
    float xr0 = lbias[0], xr1 = lbias[1], xl0 = lbias[0], xl1 = lbias[1];
#pragma unroll
    for (int k = 0; k < 64; ++k) {
        float w0 = lW[k], w1 = lW[64 + k];
        float a = lr[(size_t)k * NSAMP], bb2 = ll[(size_t)k * NSAMP];
        xr0 = fmaf(a, w0, xr0); xr1 = fmaf(a, w1, xr1);
        xl0 = fmaf(bb2, w0, xl0); xl1 = fmaf(bb2, w1, xl1);
    }
    float xv0 = vbias[0], xv1 = vbias[1];
#pragma unroll
    for (int k = 0; k < 64; ++k) {
        float a = vl[(size_t)k * NSAMP];
        xv0 = fmaf(a, vW[k], xv0); xv1 = fmaf(a, vW[128 + k], xv1);
    }
#pragma unroll
    for (int k = 0; k < 64; ++k) {
        float a = vr[(size_t)k * NSAMP];
        xv0 = fmaf(a, vW[64 + k], xv0); xv1 = fmaf(a, vW[192 + k], xv1);
    }
    out[2 * b]     = xr0 * m_r + xl0 * m_l + xv0 * m_vor;
    out[2 * b + 1] = xr1 * m_r + xl1 * m_l + xv1 * m_vor;
}

extern "C" void kernel_launch(void* const* d_in, const int* in_sizes, int n_in,
                              void* d_out, int out_size)
{
    (void)in_sizes; (void)n_in; (void)out_size;
    const float* dir   = (const float*)d_in[0];
    const float* pos   = (const float*)d_in[1];
    const float* lWih0 = (const float*)d_in[2];
    const float* lWhh0 = (const float*)d_in[3];
    const float* lb0   = (const float*)d_in[4];
    const float* lWih1 = (const float*)d_in[5];
    const float* lWhh1 = (const float*)d_in[6];
    const float* lb1   = (const float*)d_in[7];
    const float* vWih0 = (const float*)d_in[8];
    const float* vWhh0 = (const float*)d_in[9];
    const float* vb0   = (const float*)d_in[10];
    const float* vWih1 = (const float*)d_in[11];
    const float* vWhh1 = (const float*)d_in[12];
    const float* vb1   = (const float*)d_in[13];
    const float* lfcW  = (const float*)d_in[14];
    const float* lfcb  = (const float*)d_in[15];
    const float* vfcW  = (const float*)d_in[16];
    const float* vfcb  = (const float*)d_in[17];
    float* out = (float*)d_out;

    cudaFuncSetAttribute(mma_layer0, cudaFuncAttributeMaxDynamicSharedMemorySize, SMEM_L0);
    cudaFuncSetAttribute(mma_layer1, cudaFuncAttributeMaxDynamicSharedMemorySize, SMEM_L1);

    k_transpose<<<NSAMP / 128, 128>>>(pos);
    mma_layer0<<<dim3(NSAMP / 128, 2, 2), 128, SMEM_L0>>>(lWih0, lWhh0, lb0, vWih0, vWhh0, vb0);
    mma_layer1<<<dim3(NSAMP / 128, 2), 128, SMEM_L1>>>(lWih1, lWhh1, lb1, vWih1, vWhh1, vb1);
    head_kernel<<<256, 128>>>(dir, lfcW, lfcb, vfcW, vfcb, out);
}

// round 15
// speedup vs baseline: 3.7816x; 1.4685x over previous
#include <cuda_runtime.h>
#include <cuda_fp16.h>
#include <cstdint>

#define NSAMP 65536
#define BORIG 32768
#define TT    15
typedef unsigned long long u64;

__device__ u64      g_xT[(size_t)30 * NSAMP];
__device__ uint32_t g_l0u[(size_t)2 * TT * 32 * NSAMP];   // fp16x2 pairs, ~251 MB
__device__ float    g_last[(size_t)2 * 64 * NSAMP];

__device__ __forceinline__ u64 pack2(float lo, float hi) {
    u64 r; asm("mov.b64 %0, {%1, %2};" : "=l"(r) : "r"(__float_as_uint(lo)), "r"(__float_as_uint(hi))); return r;
}
__device__ __forceinline__ void unpack2(u64 a, float& lo, float& hi) {
    unsigned x, y; asm("mov.b64 {%0, %1}, %2;" : "=r"(x), "=r"(y) : "l"(a));
    lo = __uint_as_float(x); hi = __uint_as_float(y);
}
__device__ __forceinline__ float tanhx(float x) { float r; asm("tanh.approx.f32 %0, %1;" : "=f"(r) : "f"(x)); return r; }
__device__ __forceinline__ float sigf(float x) { return fmaf(0.5f, tanhx(0.5f * x), 0.5f); }
__device__ __forceinline__ uint32_t hpack(float lo, float hi) {
    uint32_t r; asm("cvt.rn.f16x2.f32 %0, %1, %2;" : "=r"(r) : "f"(hi), "f"(lo)); return r;
}
__device__ __forceinline__ float f16v(float x) { return __half2float(__float2half_rn(x)); }

__device__ __forceinline__ void mma16816(float* d, const uint32_t* a, const uint32_t* b) {
    asm volatile("mma.sync.aligned.m16n8k16.row.col.f32.f16.f16.f32 "
        "{%0,%1,%2,%3}, {%4,%5,%6,%7}, {%8,%9}, {%0,%1,%2,%3};"
        : "+f"(d[0]), "+f"(d[1]), "+f"(d[2]), "+f"(d[3])
        : "r"(a[0]), "r"(a[1]), "r"(a[2]), "r"(a[3]), "r"(b[0]), "r"(b[1]));
}

// Split-N HMMA mainloop: warp (wm, wn) does 32 samples (rows 32*wm..) x 64 gates
// (g4 = 2*wn+gg, gate 0..3 -> nt = g4 + 4*gate). d[mt][gg*4+gate][4].
template<int NKT, int KP>
__device__ __forceinline__ void mma_main(float (&d)[2][8][4], const uint32_t* A32,
                                         const uint32_t* B32, int wm, int wn, int l)
{
    const int r0 = 32 * wm + (l >> 2);
    const int kb = l & 3;
#pragma unroll 1
    for (int kt = 0; kt < NKT; ++kt) {
        const int ko = kt * 8 + kb;
        uint32_t a[2][4];
#pragma unroll
        for (int mt = 0; mt < 2; ++mt) {
            int aw = (r0 + 16 * mt) * KP + ko;
            a[mt][0] = A32[aw];     a[mt][1] = A32[aw + 8 * KP];
            a[mt][2] = A32[aw + 4]; a[mt][3] = A32[aw + 8 * KP + 4];
        }
#pragma unroll
        for (int gg = 0; gg < 2; ++gg)
#pragma unroll
            for (int gate = 0; gate < 4; ++gate) {
                int nt = 2 * wn + gg + 4 * gate;
                int bw = (nt * 8 + (l >> 2)) * KP + ko;
                uint32_t b[2] = { B32[bw], B32[bw + 4] };
                mma16816(d[0][gg * 4 + gate], a[0], b);
                mma16816(d[1][gg * 4 + gate], a[1], b);
            }
    }
}

// ---------------- transpose ----------------
__global__ void __launch_bounds__(128) k_transpose(const float* __restrict__ pos)
{
    __shared__ float sx[128 * 60];
    const unsigned s0 = blockIdx.x * 128u;
    for (int idx = threadIdx.x; idx < 128 * 60; idx += 128) {
        int i = idx / 60, f = idx % 60;
        unsigned s = s0 + i;
        sx[idx] = pos[s < BORIG ? (size_t)s * 120 + f : (size_t)(s - BORIG) * 120 + 60 + f];
    }
    __syncthreads();
    const int i = threadIdx.x;
#pragma unroll
    for (int u = 0; u < 30; ++u) {
        int t = u >> 1, p = u & 1;
        g_xT[(size_t)u * NSAMP + s0 + i] = pack2(sx[i * 60 + t * 4 + p * 2], sx[i * 60 + t * 4 + p * 2 + 1]);
    }
}

// ---------------- layer0: K halves [x 0..3 | h 4..35 | bias 36,37] -> 3 kt, KP=28 words
#define SMEM_L0 ((128 * 28 + 128 * 28) * 4)
__global__ void __launch_bounds__(256, 2) mma_layer0(
    const float* __restrict__ lWih, const float* __restrict__ lWhh, const float* __restrict__ lb,
    const float* __restrict__ vWih, const float* __restrict__ vWhh, const float* __restrict__ vb)
{
    extern __shared__ __align__(16) char sm0[];
    uint32_t* A32 = reinterpret_cast<uint32_t*>(sm0);
    __half* Bh = reinterpret_cast<__half*>(sm0 + 128 * 28 * 4);
    const uint32_t* B32 = reinterpret_cast<const uint32_t*>(Bh);
    const int tid = threadIdx.x, w = tid >> 5, l = tid & 31;
    const int wm = w & 3, wn = w >> 2;
    const int br = blockIdx.y, dd = blockIdx.z;
    const unsigned s0 = blockIdx.x * 128u;
    const float* Wih = (br ? vWih : lWih) + dd * 128 * 4;
    const float* Whh = (br ? vWhh : lWhh) + dd * 128 * 32;
    const float* bbp = (br ? vb   : lb  ) + dd * 128;

    for (int idx = tid; idx < 128 * 56; idx += 256) {
        int r = idx / 56, k = idx % 56;
        float wv = 0.f;
        if (k < 36)        wv = (k < 4) ? Wih[r * 4 + k] : Whh[r * 32 + k - 4];
        else if (k == 36)  wv = f16v(bbp[r]);
        else if (k == 37)  wv = bbp[r] - f16v(bbp[r]);
        Bh[r * 56 + k] = __float2half_rn(wv);
    }
    for (int idx = tid; idx < 128 * 28; idx += 256) A32[idx] = 0;
    __syncthreads();
    if (tid < 128) A32[tid * 28 + 18] = 0x3C003C00u;
    __syncthreads();

    float c[2][2][2][2];
#pragma unroll
    for (int a = 0; a < 2; ++a)
#pragma unroll
        for (int b = 0; b < 2; ++b)
#pragma unroll
            for (int g = 0; g < 2; ++g) { c[a][b][g][0] = 0.f; c[a][b][g][1] = 0.f; }

#pragma unroll 1
    for (int step = 0; step < TT; ++step) {
        const int t = dd ? (TT - 1 - step) : step;
        if (tid < 128) {
            float f0, f1, f2, f3;
            unpack2(g_xT[(size_t)(2 * t) * NSAMP + s0 + tid], f0, f1);
            unpack2(g_xT[(size_t)(2 * t + 1) * NSAMP + s0 + tid], f2, f3);
            A32[tid * 28]     = hpack(f0, f1);
            A32[tid * 28 + 1] = hpack(f2, f3);
        }
        __syncthreads();

        float d[2][8][4];
#pragma unroll
        for (int mt = 0; mt < 2; ++mt)
#pragma unroll
            for (int nt = 0; nt < 8; ++nt)
#pragma unroll
                for (int q = 0; q < 4; ++q) d[mt][nt][q] = 0.f;
        mma_main<3, 28>(d, A32, B32, wm, wn, l);
        __syncthreads();

#pragma unroll
        for (int mt = 0; mt < 2; ++mt)
#pragma unroll
            for (int hp = 0; hp < 2; ++hp)
#pragma unroll
                for (int gg = 0; gg < 2; ++gg) {
                    float hv[2];
#pragma unroll
                    for (int col = 0; col < 2; ++col) {
                        int e = hp * 2 + col;
                        float cc = c[mt][hp][gg][col];
                        cc = sigf(d[mt][gg * 4 + 1][e]) * cc + sigf(d[mt][gg * 4][e]) * tanhx(d[mt][gg * 4 + 2][e]);
                        c[mt][hp][gg][col] = cc;
                        hv[col] = sigf(d[mt][gg * 4 + 3][e]) * tanhx(cc);
                    }
                    int srow = 32 * wm + 16 * mt + (l >> 2) + 8 * hp;
                    int jp = 8 * (2 * wn + gg) + (l & 3) * 2;
                    uint32_t hp2 = hpack(hv[0], hv[1]);
                    g_l0u[((size_t)(br * TT + t) * 32 + dd * 16 + (jp >> 1)) * NSAMP + s0 + srow] = hp2;
                    if (step < TT - 1)
                        A32[srow * 28 + 2 + (jp >> 1)] = hp2;
                }
    }
}

// ---------------- layer1: K halves [x 0..63 | h 64..95 | bias 96,97] -> 7 kt, KP=60 words
#define SMEM_L1 ((128 * 60 + 128 * 60) * 4)
__global__ void __launch_bounds__(256, 2) mma_layer1(
    const float* __restrict__ lWih, const float* __restrict__ lWhh, const float* __restrict__ lb,
    const float* __restrict__ vWih, const float* __restrict__ vWhh, const float* __restrict__ vb)
{
    extern __shared__ __align__(16) char sm[];
    uint32_t* A32 = reinterpret_cast<uint32_t*>(sm);
    __half* Bh = reinterpret_cast<__half*>(sm + 128 * 60 * 4);
    const uint32_t* B32 = reinterpret_cast<const uint32_t*>(Bh);
    const int tid = threadIdx.x, w = tid >> 5, l = tid & 31;
    const int wm = w & 3, wn = w >> 2;
    const int br = blockIdx.y;
    const unsigned s0 = blockIdx.x * 128u;
    const float* Wih = br ? vWih : lWih;
    const float* Whh = br ? vWhh : lWhh;
    const float* bbp = br ? vb : lb;

    for (int idx = tid; idx < 128 * 120; idx += 256) {
        int r = idx / 120, k = idx % 120;
        float wv = 0.f;
        if (k < 96)        wv = (k < 64) ? Wih[r * 64 + k] : Whh[r * 32 + k - 64];
        else if (k == 96)  wv = f16v(bbp[r]);
        else if (k == 97)  wv = bbp[r] - f16v(bbp[r]);
        Bh[r * 120 + k] = __float2half_rn(wv);
    }
    for (int idx = tid; idx < 128 * 60; idx += 256) A32[idx] = 0;
    __syncthreads();
    if (tid < 128) A32[tid * 60 + 48] = 0x3C003C00u;
    __syncthreads();

    const int smp = tid & 127, kb16 = (tid >> 7) * 16;

    float c[2][2][2][2];
#pragma unroll
    for (int a = 0; a < 2; ++a)
#pragma unroll
        for (int b = 0; b < 2; ++b)
#pragma unroll
            for (int g = 0; g < 2; ++g) { c[a][b][g][0] = 0.f; c[a][b][g][1] = 0.f; }

#pragma unroll 1
    for (int t = 0; t < TT; ++t) {
        const uint32_t* gx = g_l0u + (size_t)(br * TT + t) * 32 * NSAMP + s0 + smp;
#pragma unroll
        for (int i = 0; i < 16; ++i)
            A32[smp * 60 + kb16 + i] = gx[(size_t)(kb16 + i) * NSAMP];
        __syncthreads();

        float d[2][8][4];
#pragma unroll
        for (int mt = 0; mt < 2; ++mt)
#pragma unroll
            for (int nt = 0; nt < 8; ++nt)
#pragma unroll
                for (int q = 0; q < 4; ++q) d[mt][nt][q] = 0.f;
        mma_main<7, 60>(d, A32, B32, wm, wn, l);
        __syncthreads();

#pragma unroll
        for (int mt = 0; mt < 2; ++mt)
#pragma unroll
            for (int hp = 0; hp < 2; ++hp)
#pragma unroll
                for (int gg = 0; gg < 2; ++gg) {
                    float hv[2];
#pragma unroll
                    for (int col = 0; col < 2; ++col) {
                        int e = hp * 2 + col;
                        float cc = c[mt][hp][gg][col];
                        cc = sigf(d[mt][gg * 4 + 1][e]) * cc + sigf(d[mt][gg * 4][e]) * tanhx(d[mt][gg * 4 + 2][e]);
                        c[mt][hp][gg][col] = cc;
                        hv[col] = sigf(d[mt][gg * 4 + 3][e]) * tanhx(cc);
                    }
                    int srow = 32 * wm + 16 * mt + (l >> 2) + 8 * hp;
                    int jp = 8 * (2 * wn + gg) + (l & 3) * 2;
                    if (t < TT - 1) {
                        A32[srow * 60 + 32 + (jp >> 1)] = hpack(hv[0], hv[1]);
                    } else {
                        g_last[((size_t)br * 64 + jp) * NSAMP + s0 + srow]     = hv[0];
                        g_last[((size_t)br * 64 + jp + 1) * NSAMP + s0 + srow] = hv[1];
                    }
                }
    }
    __syncthreads();

    // rewrite B with bwd weights (h slots zero); bwd single step on x14 still staged in A
    for (int idx = tid; idx < 128 * 120; idx += 256) {
        int r = idx / 120, k = idx % 120;
        float wv = 0.f;
        if (k < 64)        wv = Wih[8192 + r * 64 + k];
        else if (k == 96)  wv = f16v(bbp[128 + r]);
        else if (k == 97)  wv = bbp[128 + r] - f16v(bbp[128 + r]);
        Bh[r * 120 + k] = __float2half_rn(wv);
    }
    __syncthreads();

    float d[2][8][4];
#pragma unroll
    for (int mt = 0; mt < 2; ++mt)
#pragma unroll
        for (int nt = 0; nt < 8; ++nt)
#pragma unroll
            for (int q = 0; q < 4; ++q) d[mt][nt][q] = 0.f;
    mma_main<7, 60>(d, A32, B32, wm, wn, l);
#pragma unroll
    for (int mt = 0; mt < 2; ++mt)
#pragma unroll
        for (int hp = 0; hp < 2; ++hp)
#pragma unroll
            for (int gg = 0; gg < 2; ++gg) {
                int srow = 32 * wm + 16 * mt + (l >> 2) + 8 * hp;
                int jp = 8 * (2 * wn + gg) + (l & 3) * 2;
#pragma unroll
                for (int col = 0; col < 2; ++col) {
                    int e = hp * 2 + col;
                    float cn = sigf(d[mt][gg * 4][e]) * tanhx(d[mt][gg * 4 + 2][e]);   // c0 = 0
                    g_last[((size_t)br * 64 + 32 + jp + col) * NSAMP + s0 + srow] =
                        sigf(d[mt][gg * 4 + 3][e]) * tanhx(cn);
                }
            }
}

// ---------------- head: chunked loads for MLP ----------------
__global__ void __launch_bounds__(128) head_kernel(
    const float* __restrict__ dir,
    const float* __restrict__ lW, const float* __restrict__ lbias,
    const float* __restrict__ vW, const float* __restrict__ vbias,
    float* __restrict__ out)
{
    const int b = blockIdx.x * 128 + threadIdx.x;
    if (b >= BORIG) return;
    const float* di = dir + (size_t)b * 6;
    int am = 0; float mv = di[0];
#pragma unroll
    for (int i = 1; i < 6; ++i) { float x = di[i]; if (x > mv) { mv = x; am = i; } }
    const float m_vor = (am == 1 || am == 4) ? 1.f : 0.f;
    const float m_r   = (am == 0 || am == 5) ? 1.f : 0.f;
    const float m_l   = (am == 2 || am == 3) ? 1.f : 0.f;
    const float* ll = g_last + b;
    const float* lr = g_last + b + BORIG;
    const float* vl = g_last + (size_t)64 * NSAMP + b;
    const float* vr = g_last + (size_t)64 * NSAMP + b + BORIG;

    float xr0 = lbias[0], xr1 = lbias[1], xl0 = lbias[0], xl1 = lbias[1];
    float xv0 = vbias[0], xv1 = vbias[1];
#pragma unroll
    for (int kb = 0; kb < 64; kb += 16) {
        float aL[16], aR[16], aVL[16], aVR[16];
#pragma unroll
        for (int i = 0; i < 16; ++i) {
            aL[i]  = ll[(size_t)(kb + i) * NSAMP];
            aR[i]  = lr[(size_t)(kb + i) * NSAMP];
            aVL[i] = vl[(size_t)(kb + i) * NSAMP];
            aVR[i] = vr[(size_t)(kb + i) * NSAMP];
        }
#pragma unroll
        for (int i = 0; i < 16; ++i) {
            int k = kb + i;
            float w0 = lW[k], w1 = lW[64 + k];
            xr0 = fmaf(aR[i], w0, xr0); xr1 = fmaf(aR[i], w1, xr1);
            xl0 = fmaf(aL[i], w0, xl0); xl1 = fmaf(aL[i], w1, xl1);
            xv0 = fmaf(aVL[i], vW[k], xv0);       xv1 = fmaf(aVL[i], vW[128 + k], xv1);
            xv0 = fmaf(aVR[i], vW[64 + k], xv0);  xv1 = fmaf(aVR[i], vW[192 + k], xv1);
        }
    }
    out[2 * b]     = xr0 * m_r + xl0 * m_l + xv0 * m_vor;
    out[2 * b + 1] = xr1 * m_r + xl1 * m_l + xv1 * m_vor;
}

extern "C" void kernel_launch(void* const* d_in, const int* in_sizes, int n_in,
                              void* d_out, int out_size)
{
    (void)in_sizes; (void)n_in; (void)out_size;
    const float* dir   = (const float*)d_in[0];
    const float* pos   = (const float*)d_in[1];
    const float* lWih0 = (const float*)d_in[2];
    const float* lWhh0 = (const float*)d_in[3];
    const float* lb0   = (const float*)d_in[4];
    const float* lWih1 = (const float*)d_in[5];
    const float* lWhh1 = (const float*)d_in[6];
    const float* lb1   = (const float*)d_in[7];
    const float* vWih0 = (const float*)d_in[8];
    const float* vWhh0 = (const float*)d_in[9];
    const float* vb0   = (const float*)d_in[10];
    const float* vWih1 = (const float*)d_in[11];
    const float* vWhh1 = (const float*)d_in[12];
    const float* vb1   = (const float*)d_in[13];
    const float* lfcW  = (const float*)d_in[14];
    const float* lfcb  = (const float*)d_in[15];
    const float* vfcW  = (const float*)d_in[16];
    const float* vfcb  = (const float*)d_in[17];
    float* out = (float*)d_out;

    cudaFuncSetAttribute(mma_layer0, cudaFuncAttributeMaxDynamicSharedMemorySize, SMEM_L0);
    cudaFuncSetAttribute(mma_layer1, cudaFuncAttributeMaxDynamicSharedMemorySize, SMEM_L1);

    k_transpose<<<NSAMP / 128, 128>>>(pos);
    mma_layer0<<<dim3(NSAMP / 128, 2, 2), 256, SMEM_L0>>>(lWih0, lWhh0, lb0, vWih0, vWhh0, vb0);
    mma_layer1<<<dim3(NSAMP / 128, 2), 256, SMEM_L1>>>(lWih1, lWhh1, lb1, vWih1, vWhh1, vb1);
    head_kernel<<<256, 128>>>(dir, lfcW, lfcb, vfcW, vfcb, out);
}

// round 16
// speedup vs baseline: 4.4180x; 1.1683x over previous
#include <cuda_runtime.h>
#include <cuda_fp16.h>
#include <cstdint>

#define NSAMP 65536
#define BORIG 32768
#define TT    15
typedef unsigned long long u64;

__device__ u64      g_xT[(size_t)30 * NSAMP];
__device__ uint32_t g_l0u[(size_t)2 * TT * 32 * NSAMP];   // fp16x2 pairs
__device__ float    g_last[(size_t)2 * 64 * NSAMP];

__device__ __forceinline__ u64 pack2(float lo, float hi) {
    u64 r; asm("mov.b64 %0, {%1, %2};" : "=l"(r) : "r"(__float_as_uint(lo)), "r"(__float_as_uint(hi))); return r;
}
__device__ __forceinline__ void unpack2(u64 a, float& lo, float& hi) {
    unsigned x, y; asm("mov.b64 {%0, %1}, %2;" : "=r"(x), "=r"(y) : "l"(a));
    lo = __uint_as_float(x); hi = __uint_as_float(y);
}
__device__ __forceinline__ float tanhx(float x) { float r; asm("tanh.approx.f32 %0, %1;" : "=f"(r) : "f"(x)); return r; }
__device__ __forceinline__ float sigf(float x) { return fmaf(0.5f, tanhx(0.5f * x), 0.5f); }
__device__ __forceinline__ uint32_t hpack(float lo, float hi) {
    uint32_t r; asm("cvt.rn.f16x2.f32 %0, %1, %2;" : "=r"(r) : "f"(hi), "f"(lo)); return r;
}
__device__ __forceinline__ float f16v(float x) { return __half2float(__float2half_rn(x)); }

__device__ __forceinline__ void mma16816(float* d, const uint32_t* a, const uint32_t* b) {
    asm volatile("mma.sync.aligned.m16n8k16.row.col.f32.f16.f16.f32 "
        "{%0,%1,%2,%3}, {%4,%5,%6,%7}, {%8,%9}, {%0,%1,%2,%3};"
        : "+f"(d[0]), "+f"(d[1]), "+f"(d[2]), "+f"(d[3])
        : "r"(a[0]), "r"(a[1]), "r"(a[2]), "r"(a[3]), "r"(b[0]), "r"(b[1]));
}

// Split-N HMMA mainloop: warp (wm, wn) -> 32 samples x 64 gates (gg in {0,1}, gate 0..3).
template<int NKT, int KP>
__device__ __forceinline__ void mma_main(float (&d)[2][8][4], const uint32_t* A32,
                                         const uint32_t* B32, int wm, int wn, int l)
{
    const int r0 = 32 * wm + (l >> 2);
    const int kb = l & 3;
#pragma unroll 1
    for (int kt = 0; kt < NKT; ++kt) {
        const int ko = kt * 8 + kb;
        uint32_t a[2][4];
#pragma unroll
        for (int mt = 0; mt < 2; ++mt) {
            int aw = (r0 + 16 * mt) * KP + ko;
            a[mt][0] = A32[aw];     a[mt][1] = A32[aw + 8 * KP];
            a[mt][2] = A32[aw + 4]; a[mt][3] = A32[aw + 8 * KP + 4];
        }
#pragma unroll
        for (int gg = 0; gg < 2; ++gg)
#pragma unroll
            for (int gate = 0; gate < 4; ++gate) {
                int nt = 2 * wn + gg + 4 * gate;
                int bw = (nt * 8 + (l >> 2)) * KP + ko;
                uint32_t b[2] = { B32[bw], B32[bw + 4] };
                mma16816(d[0][gg * 4 + gate], a[0], b);
                mma16816(d[1][gg * 4 + gate], a[1], b);
            }
    }
}

// ---------------- transpose ----------------
__global__ void __launch_bounds__(128) k_transpose(const float* __restrict__ pos)
{
    __shared__ float sx[128 * 60];
    const unsigned s0 = blockIdx.x * 128u;
    for (int idx = threadIdx.x; idx < 128 * 60; idx += 128) {
        int i = idx / 60, f = idx % 60;
        unsigned s = s0 + i;
        sx[idx] = pos[s < BORIG ? (size_t)s * 120 + f : (size_t)(s - BORIG) * 120 + 60 + f];
    }
    __syncthreads();
    const int i = threadIdx.x;
#pragma unroll
    for (int u = 0; u < 30; ++u) {
        int t = u >> 1, p = u & 1;
        g_xT[(size_t)u * NSAMP + s0 + i] = pack2(sx[i * 60 + t * 4 + p * 2], sx[i * 60 + t * 4 + p * 2 + 1]);
    }
}

// ---------------- layer0: K halves [x 0..3 | h 4..35 | bias 36,37] -> 3 kt, KP=28 words
#define SMEM_L0 ((128 * 28 + 128 * 28) * 4)
__global__ void __launch_bounds__(256, 2) mma_layer0(
    const float* __restrict__ lWih, const float* __restrict__ lWhh, const float* __restrict__ lb,
    const float* __restrict__ vWih, const float* __restrict__ vWhh, const float* __restrict__ vb)
{
    extern __shared__ __align__(16) char sm0[];
    uint32_t* A32 = reinterpret_cast<uint32_t*>(sm0);
    __half* Bh = reinterpret_cast<__half*>(sm0 + 128 * 28 * 4);
    const uint32_t* B32 = reinterpret_cast<const uint32_t*>(Bh);
    const int tid = threadIdx.x, w = tid >> 5, l = tid & 31;
    const int wm = w & 3, wn = w >> 2;
    const int br = blockIdx.y, dd = blockIdx.z;
    const unsigned s0 = blockIdx.x * 128u;
    const float* Wih = (br ? vWih : lWih) + dd * 128 * 4;
    const float* Whh = (br ? vWhh : lWhh) + dd * 128 * 32;
    const float* bbp = (br ? vb   : lb  ) + dd * 128;

    for (int idx = tid; idx < 128 * 56; idx += 256) {
        int r = idx / 56, k = idx % 56;
        float wv = 0.f;
        if (k < 36)        wv = (k < 4) ? Wih[r * 4 + k] : Whh[r * 32 + k - 4];
        else if (k == 36)  wv = f16v(bbp[r]);
        else if (k == 37)  wv = bbp[r] - f16v(bbp[r]);
        Bh[r * 56 + k] = __float2half_rn(wv);
    }
    for (int idx = tid; idx < 128 * 28; idx += 256) A32[idx] = 0;
    __syncthreads();
    if (tid < 128) A32[tid * 28 + 18] = 0x3C003C00u;
    __syncthreads();

    float c[2][2][2][2];
#pragma unroll
    for (int a = 0; a < 2; ++a)
#pragma unroll
        for (int b = 0; b < 2; ++b)
#pragma unroll
            for (int g = 0; g < 2; ++g) { c[a][b][g][0] = 0.f; c[a][b][g][1] = 0.f; }

#pragma unroll 1
    for (int step = 0; step < TT; ++step) {
        const int t = dd ? (TT - 1 - step) : step;
        if (tid < 128) {
            float f0, f1, f2, f3;
            unpack2(g_xT[(size_t)(2 * t) * NSAMP + s0 + tid], f0, f1);
            unpack2(g_xT[(size_t)(2 * t + 1) * NSAMP + s0 + tid], f2, f3);
            A32[tid * 28]     = hpack(f0, f1);
            A32[tid * 28 + 1] = hpack(f2, f3);
        }
        __syncthreads();

        float d[2][8][4];
#pragma unroll
        for (int mt = 0; mt < 2; ++mt)
#pragma unroll
            for (int nt = 0; nt < 8; ++nt)
#pragma unroll
                for (int q = 0; q < 4; ++q) d[mt][nt][q] = 0.f;
        mma_main<3, 28>(d, A32, B32, wm, wn, l);
        __syncthreads();

#pragma unroll
        for (int mt = 0; mt < 2; ++mt)
#pragma unroll
            for (int hp = 0; hp < 2; ++hp)
#pragma unroll
                for (int gg = 0; gg < 2; ++gg) {
                    float hv[2];
#pragma unroll
                    for (int col = 0; col < 2; ++col) {
                        int e = hp * 2 + col;
                        float cc = c[mt][hp][gg][col];
                        cc = sigf(d[mt][gg * 4 + 1][e]) * cc + sigf(d[mt][gg * 4][e]) * tanhx(d[mt][gg * 4 + 2][e]);
                        c[mt][hp][gg][col] = cc;
                        hv[col] = sigf(d[mt][gg * 4 + 3][e]) * tanhx(cc);
                    }
                    int srow = 32 * wm + 16 * mt + (l >> 2) + 8 * hp;
                    int jp = 8 * (2 * wn + gg) + (l & 3) * 2;
                    uint32_t hp2 = hpack(hv[0], hv[1]);
                    g_l0u[((size_t)(br * TT + t) * 32 + dd * 16 + (jp >> 1)) * NSAMP + s0 + srow] = hp2;
                    if (step < TT - 1)
                        A32[srow * 28 + 2 + (jp >> 1)] = hp2;
                }
    }
}

// ---------------- layer1: K halves [x 0..63 | h 64..95] -> 6 kt, KP=52 words; bias in epilogue regs
#define SMEM_L1 ((128 * 52 + 128 * 52) * 4)
__global__ void __launch_bounds__(256, 2) mma_layer1(
    const float* __restrict__ lWih, const float* __restrict__ lWhh, const float* __restrict__ lb,
    const float* __restrict__ vWih, const float* __restrict__ vWhh, const float* __restrict__ vb)
{
    extern __shared__ __align__(16) char sm[];
    uint32_t* A32 = reinterpret_cast<uint32_t*>(sm);
    __half* Bh = reinterpret_cast<__half*>(sm + 128 * 52 * 4);
    const uint32_t* B32 = reinterpret_cast<const uint32_t*>(Bh);
    const int tid = threadIdx.x, w = tid >> 5, l = tid & 31;
    const int wm = w & 3, wn = w >> 2;
    const int br = blockIdx.y;
    const unsigned s0 = blockIdx.x * 128u;
    const float* Wih = br ? vWih : lWih;
    const float* Whh = br ? vWhh : lWhh;
    const float* bbp = br ? vb : lb;

    for (int idx = tid; idx < 128 * 104; idx += 256) {
        int r = idx / 104, k = idx % 104;
        float wv = 0.f;
        if (k < 96) wv = (k < 64) ? Wih[r * 64 + k] : Whh[r * 32 + k - 64];
        Bh[r * 104 + k] = __float2half_rn(wv);
    }
    for (int idx = tid; idx < 128 * 52; idx += 256) A32[idx] = 0;
    __syncthreads();

    // per-thread fwd biases: r = gate*32 + 8*(2wn+gg) + (l&3)*2 + col
    float bF[2][4][2];
#pragma unroll
    for (int gg = 0; gg < 2; ++gg)
#pragma unroll
        for (int gate = 0; gate < 4; ++gate)
#pragma unroll
            for (int col = 0; col < 2; ++col)
                bF[gg][gate][col] = bbp[gate * 32 + 8 * (2 * wn + gg) + (l & 3) * 2 + col];

    const int smp = tid & 127, kb16 = (tid >> 7) * 16;
    const uint32_t* gbase = g_l0u + (size_t)br * TT * 32 * NSAMP + s0 + smp;

    float c[2][2][2][2];
#pragma unroll
    for (int a = 0; a < 2; ++a)
#pragma unroll
        for (int b = 0; b < 2; ++b)
#pragma unroll
            for (int g = 0; g < 2; ++g) { c[a][b][g][0] = 0.f; c[a][b][g][1] = 0.f; }

    uint32_t pf[16];
#pragma unroll
    for (int i = 0; i < 16; ++i)                      // prefetch t = 0
        pf[i] = gbase[(size_t)(kb16 + i) * NSAMP];

#pragma unroll 1
    for (int t = 0; t < TT; ++t) {
#pragma unroll
        for (int i = 0; i < 16; ++i)                  // commit staged x
            A32[smp * 52 + kb16 + i] = pf[i];
        const int tn = (t < TT - 1) ? t + 1 : t;
#pragma unroll
        for (int i = 0; i < 16; ++i)                  // prefetch next (overlaps MMA)
            pf[i] = gbase[((size_t)tn * 32 + kb16 + i) * NSAMP];
        __syncthreads();

        float d[2][8][4];
#pragma unroll
        for (int mt = 0; mt < 2; ++mt)
#pragma unroll
            for (int nt = 0; nt < 8; ++nt)
#pragma unroll
                for (int q = 0; q < 4; ++q) d[mt][nt][q] = 0.f;
        mma_main<6, 52>(d, A32, B32, wm, wn, l);
        __syncthreads();

#pragma unroll
        for (int mt = 0; mt < 2; ++mt)
#pragma unroll
            for (int hp = 0; hp < 2; ++hp)
#pragma unroll
                for (int gg = 0; gg < 2; ++gg) {
                    float hv[2];
#pragma unroll
                    for (int col = 0; col < 2; ++col) {
                        int e = hp * 2 + col;
                        float iv = d[mt][gg * 4][e]     + bF[gg][0][col];
                        float fv = d[mt][gg * 4 + 1][e] + bF[gg][1][col];
                        float gv = d[mt][gg * 4 + 2][e] + bF[gg][2][col];
                        float ov = d[mt][gg * 4 + 3][e] + bF[gg][3][col];
                        float cc = c[mt][hp][gg][col];
                        cc = sigf(fv) * cc + sigf(iv) * tanhx(gv);
                        c[mt][hp][gg][col] = cc;
                        hv[col] = sigf(ov) * tanhx(cc);
                    }
                    int srow = 32 * wm + 16 * mt + (l >> 2) + 8 * hp;
                    int jp = 8 * (2 * wn + gg) + (l & 3) * 2;
                    if (t < TT - 1) {
                        A32[srow * 52 + 32 + (jp >> 1)] = hpack(hv[0], hv[1]);
                    } else {
                        g_last[((size_t)br * 64 + jp) * NSAMP + s0 + srow]     = hv[0];
                        g_last[((size_t)br * 64 + jp + 1) * NSAMP + s0 + srow] = hv[1];
                    }
                }
    }
    __syncthreads();

    // rewrite B with bwd weights (h slots zero); bwd single step on x14 still staged in A
    for (int idx = tid; idx < 128 * 104; idx += 256) {
        int r = idx / 104, k = idx % 104;
        Bh[r * 104 + k] = __float2half_rn(k < 64 ? Wih[8192 + r * 64 + k] : 0.f);
    }
    __syncthreads();

    float d[2][8][4];
#pragma unroll
    for (int mt = 0; mt < 2; ++mt)
#pragma unroll
        for (int nt = 0; nt < 8; ++nt)
#pragma unroll
            for (int q = 0; q < 4; ++q) d[mt][nt][q] = 0.f;
    mma_main<6, 52>(d, A32, B32, wm, wn, l);
#pragma unroll
    for (int mt = 0; mt < 2; ++mt)
#pragma unroll
        for (int hp = 0; hp < 2; ++hp)
#pragma unroll
            for (int gg = 0; gg < 2; ++gg) {
                int srow = 32 * wm + 16 * mt + (l >> 2) + 8 * hp;
                int jp = 8 * (2 * wn + gg) + (l & 3) * 2;
#pragma unroll
                for (int col = 0; col < 2; ++col) {
                    int e = hp * 2 + col;
                    int r = 8 * (2 * wn + gg) + (l & 3) * 2 + col;
                    float iv = d[mt][gg * 4][e]     + bbp[128 + r];
                    float gv = d[mt][gg * 4 + 2][e] + bbp[128 + 64 + r];
                    float ov = d[mt][gg * 4 + 3][e] + bbp[128 + 96 + r];
                    float cn = sigf(iv) * tanhx(gv);   // c0 = 0
                    g_last[((size_t)br * 64 + 32 + jp + col) * NSAMP + s0 + srow] =
                        sigf(ov) * tanhx(cn);
                }
            }
}

// ---------------- head: 4 threads per sample, shuffle reduce ----------------
__global__ void __launch_bounds__(256) head_kernel(
    const float* __restrict__ dir,
    const float* __restrict__ lW, const float* __restrict__ lbias,
    const float* __restrict__ vW, const float* __restrict__ vbias,
    float* __restrict__ out)
{
    const int gid = blockIdx.x * 256 + threadIdx.x;
    const int b = gid >> 2, p = gid & 3;
    if (b >= BORIG) return;
    const int k0 = p * 16;

    const float* ll = g_last + b;
    const float* lr = g_last + b + BORIG;
    const float* vl = g_last + (size_t)64 * NSAMP + b;
    const float* vr = g_last + (size_t)64 * NSAMP + b + BORIG;

    float xr0 = 0.f, xr1 = 0.f, xl0 = 0.f, xl1 = 0.f, xv0 = 0.f, xv1 = 0.f;
#pragma unroll
    for (int i = 0; i < 16; ++i) {
        int k = k0 + i;
        float aL = ll[(size_t)k * NSAMP], aR = lr[(size_t)k * NSAMP];
        float aVL = vl[(size_t)k * NSAMP], aVR = vr[(size_t)k * NSAMP];
        float w0 = lW[k], w1 = lW[64 + k];
        xr0 = fmaf(aR, w0, xr0); xr1 = fmaf(aR, w1, xr1);
        xl0 = fmaf(aL, w0, xl0); xl1 = fmaf(aL, w1, xl1);
        xv0 = fmaf(aVL, vW[k], xv0);      xv1 = fmaf(aVL, vW[128 + k], xv1);
        xv0 = fmaf(aVR, vW[64 + k], xv0); xv1 = fmaf(aVR, vW[192 + k], xv1);
    }
#pragma unroll
    for (int o = 1; o < 4; o <<= 1) {
        xr0 += __shfl_xor_sync(0xFFFFFFFF, xr0, o);
        xr1 += __shfl_xor_sync(0xFFFFFFFF, xr1, o);
        xl0 += __shfl_xor_sync(0xFFFFFFFF, xl0, o);
        xl1 += __shfl_xor_sync(0xFFFFFFFF, xl1, o);
        xv0 += __shfl_xor_sync(0xFFFFFFFF, xv0, o);
        xv1 += __shfl_xor_sync(0xFFFFFFFF, xv1, o);
    }
    if (p == 0) {
        const float* di = dir + (size_t)b * 6;
        int am = 0; float mv = di[0];
#pragma unroll
        for (int i = 1; i < 6; ++i) { float x = di[i]; if (x > mv) { mv = x; am = i; } }
        const float m_vor = (am == 1 || am == 4) ? 1.f : 0.f;
        const float m_r   = (am == 0 || am == 5) ? 1.f : 0.f;
        const float m_l   = (am == 2 || am == 3) ? 1.f : 0.f;
        out[2 * b]     = (xr0 + lbias[0]) * m_r + (xl0 + lbias[0]) * m_l + (xv0 + vbias[0]) * m_vor;
        out[2 * b + 1] = (xr1 + lbias[1]) * m_r + (xl1 + lbias[1]) * m_l + (xv1 + vbias[1]) * m_vor;
    }
}

extern "C" void kernel_launch(void* const* d_in, const int* in_sizes, int n_in,
                              void* d_out, int out_size)
{
    (void)in_sizes; (void)n_in; (void)out_size;
    const float* dir   = (const float*)d_in[0];
    const float* pos   = (const float*)d_in[1];
    const float* lWih0 = (const float*)d_in[2];
    const float* lWhh0 = (const float*)d_in[3];
    const float* lb0   = (const float*)d_in[4];
    const float* lWih1 = (const float*)d_in[5];
    const float* lWhh1 = (const float*)d_in[6];
    const float* lb1   = (const float*)d_in[7];
    const float* vWih0 = (const float*)d_in[8];
    const float* vWhh0 = (const float*)d_in[9];
    const float* vb0   = (const float*)d_in[10];
    const float* vWih1 = (const float*)d_in[11];
    const float* vWhh1 = (const float*)d_in[12];
    const float* vb1   = (const float*)d_in[13];
    const float* lfcW  = (const float*)d_in[14];
    const float* lfcb  = (const float*)d_in[15];
    const float* vfcW  = (const float*)d_in[16];
    const float* vfcb  = (const float*)d_in[17];
    float* out = (float*)d_out;

    cudaFuncSetAttribute(mma_layer0, cudaFuncAttributeMaxDynamicSharedMemorySize, SMEM_L0);
    cudaFuncSetAttribute(mma_layer1, cudaFuncAttributeMaxDynamicSharedMemorySize, SMEM_L1);

    k_transpose<<<NSAMP / 128, 128>>>(pos);
    mma_layer0<<<dim3(NSAMP / 128, 2, 2), 256, SMEM_L0>>>(lWih0, lWhh0, lb0, vWih0, vWhh0, vb0);
    mma_layer1<<<dim3(NSAMP / 128, 2), 256, SMEM_L1>>>(lWih1, lWhh1, lb1, vWih1, vWhh1, vb1);
    head_kernel<<<BORIG * 4 / 256, 256>>>(dir, lfcW, lfcb, vfcW, vfcb, out);
}

// round 17
// speedup vs baseline: 4.5873x; 1.0383x over previous
#include <cuda_runtime.h>
#include <cuda_fp16.h>
#include <cstdint>

#define NSAMP 65536
#define BORIG 32768
#define TT    15
typedef unsigned long long u64;

__device__ u64      g_xT[(size_t)30 * NSAMP];
__device__ uint32_t g_l0u[(size_t)2 * TT * 32 * NSAMP];   // fp16x2 pairs
__device__ float    g_last[(size_t)2 * 64 * NSAMP];

__device__ __forceinline__ u64 pack2(float lo, float hi) {
    u64 r; asm("mov.b64 %0, {%1, %2};" : "=l"(r) : "r"(__float_as_uint(lo)), "r"(__float_as_uint(hi))); return r;
}
__device__ __forceinline__ void unpack2(u64 a, float& lo, float& hi) {
    unsigned x, y; asm("mov.b64 {%0, %1}, %2;" : "=r"(x), "=r"(y) : "l"(a));
    lo = __uint_as_float(x); hi = __uint_as_float(y);
}
__device__ __forceinline__ float tanhx(float x) { float r; asm("tanh.approx.f32 %0, %1;" : "=f"(r) : "f"(x)); return r; }
__device__ __forceinline__ float sigf(float x) { return fmaf(0.5f, tanhx(0.5f * x), 0.5f); }
__device__ __forceinline__ uint32_t hpack(float lo, float hi) {
    uint32_t r; asm("cvt.rn.f16x2.f32 %0, %1, %2;" : "=r"(r) : "f"(hi), "f"(lo)); return r;
}
__device__ __forceinline__ float f16v(float x) { return __half2float(__float2half_rn(x)); }
__device__ __forceinline__ void barpair(int id) {
    asm volatile("bar.sync %0, 64;" :: "r"(id) : "memory");
}

__device__ __forceinline__ void mma16816(float* d, const uint32_t* a, const uint32_t* b) {
    asm volatile("mma.sync.aligned.m16n8k16.row.col.f32.f16.f16.f32 "
        "{%0,%1,%2,%3}, {%4,%5,%6,%7}, {%8,%9}, {%0,%1,%2,%3};"
        : "+f"(d[0]), "+f"(d[1]), "+f"(d[2]), "+f"(d[3])
        : "r"(a[0]), "r"(a[1]), "r"(a[2]), "r"(a[3]), "r"(b[0]), "r"(b[1]));
}

// Split-N HMMA mainloop: warp (wm, wn) -> 32 samples x 64 gates.
template<int NKT, int KP>
__device__ __forceinline__ void mma_main(float (&d)[2][8][4], const uint32_t* A32,
                                         const uint32_t* B32, int wm, int wn, int l)
{
    const int r0 = 32 * wm + (l >> 2);
    const int kb = l & 3;
#pragma unroll 1
    for (int kt = 0; kt < NKT; ++kt) {
        const int ko = kt * 8 + kb;
        uint32_t a[2][4];
#pragma unroll
        for (int mt = 0; mt < 2; ++mt) {
            int aw = (r0 + 16 * mt) * KP + ko;
            a[mt][0] = A32[aw];     a[mt][1] = A32[aw + 8 * KP];
            a[mt][2] = A32[aw + 4]; a[mt][3] = A32[aw + 8 * KP + 4];
        }
#pragma unroll
        for (int gg = 0; gg < 2; ++gg)
#pragma unroll
            for (int gate = 0; gate < 4; ++gate) {
                int nt = 2 * wn + gg + 4 * gate;
                int bw = (nt * 8 + (l >> 2)) * KP + ko;
                uint32_t b[2] = { B32[bw], B32[bw + 4] };
                mma16816(d[0][gg * 4 + gate], a[0], b);
                mma16816(d[1][gg * 4 + gate], a[1], b);
            }
    }
}

// ---------------- transpose ----------------
__global__ void __launch_bounds__(128) k_transpose(const float* __restrict__ pos)
{
    __shared__ float sx[128 * 60];
    const unsigned s0 = blockIdx.x * 128u;
    for (int idx = threadIdx.x; idx < 128 * 60; idx += 128) {
        int i = idx / 60, f = idx % 60;
        unsigned s = s0 + i;
        sx[idx] = pos[s < BORIG ? (size_t)s * 120 + f : (size_t)(s - BORIG) * 120 + 60 + f];
    }
    __syncthreads();
    const int i = threadIdx.x;
#pragma unroll
    for (int u = 0; u < 30; ++u) {
        int t = u >> 1, p = u & 1;
        g_xT[(size_t)u * NSAMP + s0 + i] = pack2(sx[i * 60 + t * 4 + p * 2], sx[i * 60 + t * 4 + p * 2 + 1]);
    }
}

// ---------------- layer0: K halves [x 0..3 | h 4..35 | bias 36,37] -> 3 kt, KP=28 words
#define SMEM_L0 ((128 * 28 + 128 * 28) * 4)
__global__ void __launch_bounds__(256, 2) mma_layer0(
    const float* __restrict__ lWih, const float* __restrict__ lWhh, const float* __restrict__ lb,
    const float* __restrict__ vWih, const float* __restrict__ vWhh, const float* __restrict__ vb)
{
    extern __shared__ __align__(16) char sm0[];
    uint32_t* A32 = reinterpret_cast<uint32_t*>(sm0);
    __half* Bh = reinterpret_cast<__half*>(sm0 + 128 * 28 * 4);
    const uint32_t* B32 = reinterpret_cast<const uint32_t*>(Bh);
    const int tid = threadIdx.x, w = tid >> 5, l = tid & 31;
    const int wm = w & 3, wn = w >> 2;
    const int br = blockIdx.y, dd = blockIdx.z;
    const unsigned s0 = blockIdx.x * 128u;
    const float* Wih = (br ? vWih : lWih) + dd * 128 * 4;
    const float* Whh = (br ? vWhh : lWhh) + dd * 128 * 32;
    const float* bbp = (br ? vb   : lb  ) + dd * 128;

    for (int idx = tid; idx < 128 * 56; idx += 256) {
        int r = idx / 56, k = idx % 56;
        float wv = 0.f;
        if (k < 36)        wv = (k < 4) ? Wih[r * 4 + k] : Whh[r * 32 + k - 4];
        else if (k == 36)  wv = f16v(bbp[r]);
        else if (k == 37)  wv = bbp[r] - f16v(bbp[r]);
        Bh[r * 56 + k] = __float2half_rn(wv);
    }
    for (int idx = tid; idx < 128 * 28; idx += 256) A32[idx] = 0;
    __syncthreads();
    if (tid < 128) A32[tid * 28 + 18] = 0x3C003C00u;
    __syncthreads();

    float c[2][2][2][2];
#pragma unroll
    for (int a = 0; a < 2; ++a)
#pragma unroll
        for (int b = 0; b < 2; ++b)
#pragma unroll
            for (int g = 0; g < 2; ++g) { c[a][b][g][0] = 0.f; c[a][b][g][1] = 0.f; }

#pragma unroll 1
    for (int step = 0; step < TT; ++step) {
        const int t = dd ? (TT - 1 - step) : step;
        if (tid < 128) {
            float f0, f1, f2, f3;
            unpack2(g_xT[(size_t)(2 * t) * NSAMP + s0 + tid], f0, f1);
            unpack2(g_xT[(size_t)(2 * t + 1) * NSAMP + s0 + tid], f2, f3);
            A32[tid * 28]     = hpack(f0, f1);
            A32[tid * 28 + 1] = hpack(f2, f3);
        }
        barpair(wm + 1);

        float d[2][8][4];
#pragma unroll
        for (int mt = 0; mt < 2; ++mt)
#pragma unroll
            for (int nt = 0; nt < 8; ++nt)
#pragma unroll
                for (int q = 0; q < 4; ++q) d[mt][nt][q] = 0.f;
        mma_main<3, 28>(d, A32, B32, wm, wn, l);
        barpair(wm + 1);

#pragma unroll
        for (int mt = 0; mt < 2; ++mt)
#pragma unroll
            for (int hp = 0; hp < 2; ++hp)
#pragma unroll
                for (int gg = 0; gg < 2; ++gg) {
                    float hv[2];
#pragma unroll
                    for (int col = 0; col < 2; ++col) {
                        int e = hp * 2 + col;
                        float cc = c[mt][hp][gg][col];
                        cc = sigf(d[mt][gg * 4 + 1][e]) * cc + sigf(d[mt][gg * 4][e]) * tanhx(d[mt][gg * 4 + 2][e]);
                        c[mt][hp][gg][col] = cc;
                        hv[col] = sigf(d[mt][gg * 4 + 3][e]) * tanhx(cc);
                    }
                    int srow = 32 * wm + 16 * mt + (l >> 2) + 8 * hp;
                    int jp = 8 * (2 * wn + gg) + (l & 3) * 2;
                    uint32_t hp2 = hpack(hv[0], hv[1]);
                    g_l0u[((size_t)(br * TT + t) * 32 + dd * 16 + (jp >> 1)) * NSAMP + s0 + srow] = hp2;
                    if (step < TT - 1)
                        A32[srow * 28 + 2 + (jp >> 1)] = hp2;
                }
    }
}

// ---------------- layer1: K halves [x 0..63 | h 64..95] -> 6 kt, KP=52 words; bias in epilogue regs
#define SMEM_L1 ((128 * 52 + 128 * 52) * 4)
__global__ void __launch_bounds__(256, 2) mma_layer1(
    const float* __restrict__ lWih, const float* __restrict__ lWhh, const float* __restrict__ lb,
    const float* __restrict__ vWih, const float* __restrict__ vWhh, const float* __restrict__ vb)
{
    extern __shared__ __align__(16) char sm[];
    uint32_t* A32 = reinterpret_cast<uint32_t*>(sm);
    __half* Bh = reinterpret_cast<__half*>(sm + 128 * 52 * 4);
    const uint32_t* B32 = reinterpret_cast<const uint32_t*>(Bh);
    const int tid = threadIdx.x, w = tid >> 5, l = tid & 31;
    const int wm = w & 3, wn = w >> 2;
    const int br = blockIdx.y;
    const unsigned s0 = blockIdx.x * 128u;
    const float* Wih = br ? vWih : lWih;
    const float* Whh = br ? vWhh : lWhh;
    const float* bbp = br ? vb : lb;

    for (int idx = tid; idx < 128 * 104; idx += 256) {
        int r = idx / 104, k = idx % 104;
        float wv = 0.f;
        if (k < 96) wv = (k < 64) ? Wih[r * 64 + k] : Whh[r * 32 + k - 64];
        Bh[r * 104 + k] = __float2half_rn(wv);
    }
    for (int idx = tid; idx < 128 * 52; idx += 256) A32[idx] = 0;
    __syncthreads();

    float bF[2][4][2];
#pragma unroll
    for (int gg = 0; gg < 2; ++gg)
#pragma unroll
        for (int gate = 0; gate < 4; ++gate)
#pragma unroll
            for (int col = 0; col < 2; ++col)
                bF[gg][gate][col] = bbp[gate * 32 + 8 * (2 * wn + gg) + (l & 3) * 2 + col];

    const int smp = tid & 127, kb16 = (tid >> 7) * 16;
    const uint32_t* gbase = g_l0u + (size_t)br * TT * 32 * NSAMP + s0 + smp;
    const int pairid = (smp >> 5) + 1;          // group of the rows this thread stages == wm+1

    float c[2][2][2][2];
#pragma unroll
    for (int a = 0; a < 2; ++a)
#pragma unroll
        for (int b = 0; b < 2; ++b)
#pragma unroll
            for (int g = 0; g < 2; ++g) { c[a][b][g][0] = 0.f; c[a][b][g][1] = 0.f; }

    uint32_t pf[16];
#pragma unroll
    for (int i = 0; i < 16; ++i)
        pf[i] = gbase[(size_t)(kb16 + i) * NSAMP];

#pragma unroll 1
    for (int t = 0; t < TT; ++t) {
#pragma unroll
        for (int i = 0; i < 16; ++i)
            A32[smp * 52 + kb16 + i] = pf[i];
        const int tn = (t < TT - 1) ? t + 1 : t;
#pragma unroll
        for (int i = 0; i < 16; ++i)
            pf[i] = gbase[((size_t)tn * 32 + kb16 + i) * NSAMP];
        barpair(pairid);

        float d[2][8][4];
#pragma unroll
        for (int mt = 0; mt < 2; ++mt)
#pragma unroll
            for (int nt = 0; nt < 8; ++nt)
#pragma unroll
                for (int q = 0; q < 4; ++q) d[mt][nt][q] = 0.f;
        mma_main<6, 52>(d, A32, B32, wm, wn, l);
        barpair(wm + 1);

#pragma unroll
        for (int mt = 0; mt < 2; ++mt)
#pragma unroll
            for (int hp = 0; hp < 2; ++hp)
#pragma unroll
                for (int gg = 0; gg < 2; ++gg) {
                    float hv[2];
#pragma unroll
                    for (int col = 0; col < 2; ++col) {
                        int e = hp * 2 + col;
                        float iv = d[mt][gg * 4][e]     + bF[gg][0][col];
                        float fv = d[mt][gg * 4 + 1][e] + bF[gg][1][col];
                        float gv = d[mt][gg * 4 + 2][e] + bF[gg][2][col];
                        float ov = d[mt][gg * 4 + 3][e] + bF[gg][3][col];
                        float cc = c[mt][hp][gg][col];
                        cc = sigf(fv) * cc + sigf(iv) * tanhx(gv);
                        c[mt][hp][gg][col] = cc;
                        hv[col] = sigf(ov) * tanhx(cc);
                    }
                    int srow = 32 * wm + 16 * mt + (l >> 2) + 8 * hp;
                    int jp = 8 * (2 * wn + gg) + (l & 3) * 2;
                    if (t < TT - 1) {
                        A32[srow * 52 + 32 + (jp >> 1)] = hpack(hv[0], hv[1]);
                    } else {
                        g_last[((size_t)br * 64 + jp) * NSAMP + s0 + srow]     = hv[0];
                        g_last[((size_t)br * 64 + jp + 1) * NSAMP + s0 + srow] = hv[1];
                    }
                }
    }
    __syncthreads();

    // rewrite B with bwd weights (h slots zero); bwd single step on x14 still staged in A
    for (int idx = tid; idx < 128 * 104; idx += 256) {
        int r = idx / 104, k = idx % 104;
        Bh[r * 104 + k] = __float2half_rn(k < 64 ? Wih[8192 + r * 64 + k] : 0.f);
    }
    __syncthreads();

    float d[2][8][4];
#pragma unroll
    for (int mt = 0; mt < 2; ++mt)
#pragma unroll
        for (int nt = 0; nt < 8; ++nt)
#pragma unroll
            for (int q = 0; q < 4; ++q) d[mt][nt][q] = 0.f;
    mma_main<6, 52>(d, A32, B32, wm, wn, l);
#pragma unroll
    for (int mt = 0; mt < 2; ++mt)
#pragma unroll
        for (int hp = 0; hp < 2; ++hp)
#pragma unroll
            for (int gg = 0; gg < 2; ++gg) {
                int srow = 32 * wm + 16 * mt + (l >> 2) + 8 * hp;
                int jp = 8 * (2 * wn + gg) + (l & 3) * 2;
#pragma unroll
                for (int col = 0; col < 2; ++col) {
                    int e = hp * 2 + col;
                    int r = 8 * (2 * wn + gg) + (l & 3) * 2 + col;
                    float iv = d[mt][gg * 4][e]     + bbp[128 + r];
                    float gv = d[mt][gg * 4 + 2][e] + bbp[128 + 64 + r];
                    float ov = d[mt][gg * 4 + 3][e] + bbp[128 + 96 + r];
                    float cn = sigf(iv) * tanhx(gv);   // c0 = 0
                    g_last[((size_t)br * 64 + 32 + jp + col) * NSAMP + s0 + srow] =
                        sigf(ov) * tanhx(cn);
                }
            }
}

// ---------------- head: 4 threads per sample, shuffle reduce ----------------
__global__ void __launch_bounds__(256) head_kernel(
    const float* __restrict__ dir,
    const float* __restrict__ lW, const float* __restrict__ lbias,
    const float* __restrict__ vW, const float* __restrict__ vbias,
    float* __restrict__ out)
{
    const int gid = blockIdx.x * 256 + threadIdx.x;
    const int b = gid >> 2, p = gid & 3;
    if (b >= BORIG) return;
    const int k0 = p * 16;

    const float* ll = g_last + b;
    const float* lr = g_last + b + BORIG;
    const float* vl = g_last + (size_t)64 * NSAMP + b;
    const float* vr = g_last + (size_t)64 * NSAMP + b + BORIG;

    float xr0 = 0.f, xr1 = 0.f, xl0 = 0.f, xl1 = 0.f, xv0 = 0.f, xv1 = 0.f;
#pragma unroll
    for (int i = 0; i < 16; ++i) {
        int k = k0 + i;
        float aL = ll[(size_t)k * NSAMP], aR = lr[(size_t)k * NSAMP];
        float aVL = vl[(size_t)k * NSAMP], aVR = vr[(size_t)k * NSAMP];
        float w0 = lW[k], w1 = lW[64 + k];
        xr0 = fmaf(aR, w0, xr0); xr1 = fmaf(aR, w1, xr1);
        xl0 = fmaf(aL, w0, xl0); xl1 = fmaf(aL, w1, xl1);
        xv0 = fmaf(aVL, vW[k], xv0);      xv1 = fmaf(aVL, vW[128 + k], xv1);
        xv0 = fmaf(aVR, vW[64 + k], xv0); xv1 = fmaf(aVR, vW[192 + k], xv1);
    }
#pragma unroll
    for (int o = 1; o < 4; o <<= 1) {
        xr0 += __shfl_xor_sync(0xFFFFFFFF, xr0, o);
        xr1 += __shfl_xor_sync(0xFFFFFFFF, xr1, o);
        xl0 += __shfl_xor_sync(0xFFFFFFFF, xl0, o);
        xl1 += __shfl_xor_sync(0xFFFFFFFF, xl1, o);
        xv0 += __shfl_xor_sync(0xFFFFFFFF, xv0, o);
        xv1 += __shfl_xor_sync(0xFFFFFFFF, xv1, o);
    }
    if (p == 0) {
        const float* di = dir + (size_t)b * 6;
        int am = 0; float mv = di[0];
#pragma unroll
        for (int i = 1; i < 6; ++i) { float x = di[i]; if (x > mv) { mv = x; am = i; } }
        const float m_vor = (am == 1 || am == 4) ? 1.f : 0.f;
        const float m_r   = (am == 0 || am == 5) ? 1.f : 0.f;
        const float m_l   = (am == 2 || am == 3) ? 1.f : 0.f;
        out[2 * b]     = (xr0 + lbias[0]) * m_r + (xl0 + lbias[0]) * m_l + (xv0 + vbias[0]) * m_vor;
        out[2 * b + 1] = (xr1 + lbias[1]) * m_r + (xl1 + lbias[1]) * m_l + (xv1 + vbias[1]) * m_vor;
    }
}

extern "C" void kernel_launch(void* const* d_in, const int* in_sizes, int n_in,
                              void* d_out, int out_size)
{
    (void)in_sizes; (void)n_in; (void)out_size;
    const float* dir   = (const float*)d_in[0];
    const float* pos   = (const float*)d_in[1];
    const float* lWih0 = (const float*)d_in[2];
    const float* lWhh0 = (const float*)d_in[3];
    const float* lb0   = (const float*)d_in[4];
    const float* lWih1 = (const float*)d_in[5];
    const float* lWhh1 = (const float*)d_in[6];
    const float* lb1   = (const float*)d_in[7];
    const float* vWih0 = (const float*)d_in[8];
    const float* vWhh0 = (const float*)d_in[9];
    const float* vb0   = (const float*)d_in[10];
    const float* vWih1 = (const float*)d_in[11];
    const float* vWhh1 = (const float*)d_in[12];
    const float* vb1   = (const float*)d_in[13];
    const float* lfcW  = (const float*)d_in[14];
    const float* lfcb  = (const float*)d_in[15];
    const float* vfcW  = (const float*)d_in[16];
    const float* vfcb  = (const float*)d_in[17];
    float* out = (float*)d_out;

    cudaFuncSetAttribute(mma_layer0, cudaFuncAttributeMaxDynamicSharedMemorySize, SMEM_L0);
    cudaFuncSetAttribute(mma_layer1, cudaFuncAttributeMaxDynamicSharedMemorySize, SMEM_L1);

    k_transpose<<<NSAMP / 128, 128>>>(pos);
    mma_layer0<<<dim3(NSAMP / 128, 2, 2), 256, SMEM_L0>>>(lWih0, lWhh0, lb0, vWih0, vWhh0, vb0);
    mma_layer1<<<dim3(NSAMP / 128, 2), 256, SMEM_L1>>>(lWih1, lWhh1, lb1, vWih1, vWhh1, vb1);
    head_kernel<<<BORIG * 4 / 256, 256>>>(dir, lfcW, lfcb, vfcW, vfcb, out);
}